// round 2
// baseline (speedup 1.0000x reference)
#include <cuda_runtime.h>
#include <stdint.h>

#define BB 8
#define NN 128
#define TT 8
#define LL 6
#define PP 1024
#define DD 256
#define NLABEL 40
#define BLP (BB*LL*PP)      /* 49152 */
#define M0C (1.0f/0.07f)

/* ------------- device scratch (no allocations allowed) ------------- */
__device__ float g_wn[(size_t)BB*LL*PP*DD];   /* compacted, normalized rows */
__device__ int   g_K[BB];
__device__ int   g_gate[BB];
__device__ int   g_comp2orig[BB*PP];
__device__ int   g_orig2comp[BB*PP];
__device__ int   g_clab[BB*PP];               /* labels by compact idx, pad=-1 */
__device__ int   g_cnegcnt[BB*PP];
__device__ int   g_poscnt_orig[BB*PP];
__device__ int   g_posingrp[BB*PP];
__device__ int   g_grpoff[BB*(NLABEL+1)];
__device__ int   g_grpitems[BB*PP];
__device__ int   g_idxlast_orig[BB*PP];       /* keyed by compact idx */
__device__ int   g_pospick[BLP];
__device__ float g_zp[BLP];
__device__ float g_zl[BLP];
__device__ float g_maxneg[BLP];
__device__ float g_S[BLP];
__device__ float g_partial[BB*LL];

/* ------------------- helpers ------------------- */
__device__ __forceinline__ uint32_t rotl32(uint32_t x, int r) {
    return (x << r) | (x >> (32 - r));
}

/* JAX threefry2x32 with key = jax.random.key(42) -> (0, 42) */
__device__ __forceinline__ void threefry_0_42(uint32_t& x0, uint32_t& x1) {
    const uint32_t ks0 = 0u, ks1 = 42u, ks2 = 0u ^ 42u ^ 0x1BD11BDAu;
    x0 += ks0; x1 += ks1;
#define TF_RND(r) { x0 += x1; x1 = rotl32(x1, r); x1 ^= x0; }
    TF_RND(13) TF_RND(15) TF_RND(26) TF_RND(6)  x0 += ks1; x1 += ks2 + 1u;
    TF_RND(17) TF_RND(29) TF_RND(16) TF_RND(24) x0 += ks2; x1 += ks0 + 2u;
    TF_RND(13) TF_RND(15) TF_RND(26) TF_RND(6)  x0 += ks0; x1 += ks1 + 3u;
    TF_RND(17) TF_RND(29) TF_RND(16) TF_RND(24) x0 += ks1; x1 += ks2 + 4u;
    TF_RND(13) TF_RND(15) TF_RND(26) TF_RND(6)  x0 += ks2; x1 += ks0 + 5u;
#undef TF_RND
}

/* FMA-pipe exp(x), x in [-60, 0.1]. Avoids MUFU throughput wall. */
__device__ __forceinline__ float fast_exp(float x) {
    float y = x * 1.4426950408889634f;
    int   n = __float2int_rn(y);
    float f = y - (float)n;
    float p = 1.3333558146e-3f;
    p = fmaf(p, f, 9.6181291076e-3f);
    p = fmaf(p, f, 5.5504108664e-2f);
    p = fmaf(p, f, 2.4022650695e-1f);
    p = fmaf(p, f, 6.9314718056e-1f);
    p = fmaf(p, f, 1.0f);
    return __int_as_float(__float_as_int(p) + (n << 23));
}

/* ------------------- K1: per-batch metadata ------------------- */
__global__ void k_meta(const int* __restrict__ thing, const int* __restrict__ label) {
    int b = blockIdx.x, tid = threadIdx.x;
    __shared__ int s_pack[PP];          /* 0 = invalid, else label+1 */
    __shared__ int s_cnt[NLABEL];
    __shared__ int s_off[NLABEL + 1];
    __shared__ int s_L1, s_L2, s_labL1, s_gate, s_K;
    if (tid < NLABEL) s_cnt[tid] = 0;
    if (tid == 0) { s_L1 = -1; s_L2 = -1; s_gate = 0; }
    __syncthreads();
    for (int p = tid; p < PP; p += blockDim.x) {
        int v = thing[b * PP + p];
        int lab = label[b * PP + p];
        s_pack[p] = (v != 0) ? (lab + 1) : 0;
        if (v != 0) { atomicAdd(&s_cnt[lab], 1); atomicMax(&s_L1, p); }
    }
    for (int n = tid; n < NN; n += blockDim.x) {
        int ss = 0;
        for (int t = 0; t < TT; t++) ss += thing[(b * NN + n) * TT + t];
        if (ss > 0) atomicAdd(&s_gate, 1);
    }
    __syncthreads();
    if (tid == 0) {
        int acc = 0;
        for (int v = 0; v < NLABEL; v++) { s_off[v] = acc; acc += s_cnt[v]; }
        s_off[NLABEL] = acc; s_K = acc;
        g_K[b] = acc;
        g_gate[b] = (s_gate >= 2) ? 1 : 0;
        s_labL1 = (s_L1 >= 0) ? (s_pack[s_L1] - 1) : -1;
    }
    __syncthreads();
    int labL1 = s_labL1;
    for (int p = tid; p < PP; p += blockDim.x) {
        int pk = s_pack[p];
        if (pk != 0 && (pk - 1) != labL1) atomicMax(&s_L2, p);
    }
    __syncthreads();
    int K = s_K, L1 = s_L1, L2 = s_L2;
    for (int p = tid; p < PP; p += blockDim.x) {
        int pk = s_pack[p];
        if (pk == 0) { g_orig2comp[b * PP + p] = -1; continue; }
        int crank = 0, grank = 0;
        for (int q = 0; q < p; q++) {
            int qk = s_pack[q];
            crank += (qk != 0);
            grank += (qk == pk);
        }
        int lab = pk - 1;
        g_orig2comp[b * PP + p] = crank;
        g_comp2orig[b * PP + crank] = p;
        g_clab[b * PP + crank] = lab;
        int cl = s_cnt[lab];
        g_poscnt_orig[b * PP + p] = cl - 1;
        g_cnegcnt[b * PP + crank] = K - cl;
        g_posingrp[b * PP + p] = grank;
        g_grpitems[b * PP + s_off[lab] + grank] = p;
        g_idxlast_orig[b * PP + crank] = (lab != labL1) ? L1 : L2;
    }
    if (tid <= NLABEL) g_grpoff[b * (NLABEL + 1) + tid] = s_off[tid];
    /* pad region: deterministic sentinels */
    for (int k = tid; k < PP; k += blockDim.x)
        if (k >= K) { g_clab[b * PP + k] = -1; g_cnegcnt[b * PP + k] = 0; }
}

/* ------------- K2: normalize rows, compact layout [b][l][k][d] ------------- */
__global__ void k_norm(const float* __restrict__ meta) {
    int w = (blockIdx.x * blockDim.x + threadIdx.x) >> 5;
    int lane = threadIdx.x & 31;
    int b = w / (LL * PP); int rem = w % (LL * PP);
    int l = rem / PP; int k = rem % PP;
    float* dst = g_wn + ((size_t)(b * LL + l) * PP + k) * DD;
    int K = g_K[b];
    if (k >= K) {
        float4 z = make_float4(0.f, 0.f, 0.f, 0.f);
        ((float4*)dst)[lane * 2] = z;
        ((float4*)dst)[lane * 2 + 1] = z;
        return;
    }
    int p = g_comp2orig[b * PP + k];
    int n = p >> 3, t = p & 7;
    const float* src = meta + ((((size_t)b * NN + n) * TT + t) * LL + l) * DD;
    float4 v0 = ((const float4*)src)[lane * 2];
    float4 v1 = ((const float4*)src)[lane * 2 + 1];
    float ss = v0.x*v0.x + v0.y*v0.y + v0.z*v0.z + v0.w*v0.w
             + v1.x*v1.x + v1.y*v1.y + v1.z*v1.z + v1.w*v1.w;
    for (int off = 16; off; off >>= 1) ss += __shfl_xor_sync(0xffffffffu, ss, off);
    float inv = 1.0f / fmaxf(sqrtf(ss), 1e-12f);
    v0.x*=inv; v0.y*=inv; v0.z*=inv; v0.w*=inv;
    v1.x*=inv; v1.y*=inv; v1.z*=inv; v1.w*=inv;
    ((float4*)dst)[lane * 2] = v0;
    ((float4*)dst)[lane * 2 + 1] = v1;
}

/* ------------- K3: threefry (PARTITIONABLE mode) -> random positive pick -------------
 * JAX >= 0.4.30 default: jax_threefry_partitionable=True.
 * Per element flat index i (uint64): x0 = hi32(i) = 0, x1 = lo32(i) = i,
 * hashed with key (0, 42); 32-bit output = out0 ^ out1.
 */
__global__ void k_pick(const int* __restrict__ label) {
    int i = blockIdx.x * blockDim.x + threadIdx.x;
    if (i >= BLP) return;
    int b = i / (LL * PP); int rem = i % (LL * PP);
    int l = rem / PP; int p = rem % PP;
    int k = g_orig2comp[b * PP + p];
    if (k < 0) return;
    int pc = g_poscnt_orig[b * PP + p];
    int target;
    if (pc > 0) {
        uint32_t x0 = 0u, x1 = (uint32_t)i;
        threefry_0_42(x0, x1);
        uint32_t bits = x0 ^ x1;
        float u = __uint_as_float((bits >> 9) | 0x3F800000u) - 1.0f;
        int r = (int)floorf(u * (float)pc);
        if (r > pc - 1) r = pc - 1;
        if (r < 0) r = 0;
        int lab = label[b * PP + p];
        int start = g_grpoff[b * (NLABEL + 1) + lab];
        int j = g_posingrp[b * PP + p];
        int sel = (r < j) ? r : (r + 1);
        target = g_grpitems[b * PP + start + sel];
    } else {
        target = p;   /* diag fallback */
    }
    g_pospick[(b * LL + l) * PP + k] = g_orig2comp[b * PP + target];
}

/* ------------- K4: zp / zl single-dot kernels ------------- */
__global__ void k_zpzl() {
    int w = (blockIdx.x * blockDim.x + threadIdx.x) >> 5;
    int lane = threadIdx.x & 31;
    if (w >= BLP) return;
    int b = w / (LL * PP); int rem = w % (LL * PP);
    int k = rem % PP;
    if (k >= g_K[b]) return;
    const float* base = g_wn + (size_t)w / PP * PP * DD; /* (b*LL+l)*PP*DD */
    const float* rp = base + (size_t)k * DD;
    float4 a0 = ((const float4*)rp)[lane * 2];
    float4 a1 = ((const float4*)rp)[lane * 2 + 1];
    int pick = g_pospick[w];
    const float* rq = base + (size_t)pick * DD;
    float4 q0 = ((const float4*)rq)[lane * 2];
    float4 q1 = ((const float4*)rq)[lane * 2 + 1];
    float d0 = a0.x*q0.x + a0.y*q0.y + a0.z*q0.z + a0.w*q0.w
             + a1.x*q1.x + a1.y*q1.y + a1.z*q1.z + a1.w*q1.w;
    int negc = g_cnegcnt[b * PP + k];
    float d1 = 0.f;
    if (negc > 0) {
        int lo = g_idxlast_orig[b * PP + k];
        int lc = g_orig2comp[b * PP + lo];
        const float* rl = base + (size_t)lc * DD;
        float4 c0 = ((const float4*)rl)[lane * 2];
        float4 c1 = ((const float4*)rl)[lane * 2 + 1];
        d1 = a0.x*c0.x + a0.y*c0.y + a0.z*c0.z + a0.w*c0.w
           + a1.x*c1.x + a1.y*c1.y + a1.z*c1.z + a1.w*c1.w;
    }
    for (int off = 16; off; off >>= 1) {
        d0 += __shfl_xor_sync(0xffffffffu, d0, off);
        d1 += __shfl_xor_sync(0xffffffffu, d1, off);
    }
    if (lane == 0) { g_zp[w] = d0 / 0.07f; g_zl[w] = d1 / 0.07f; }
}

/* ------------- K5: streaming GEMM + masked max / sum-exp ------------- */
#define BM 64
#define BN 128
#define BKc 16

__global__ __launch_bounds__(128) void k_lse() {
    int b = blockIdx.z, l = blockIdx.y, rt = blockIdx.x;
    int K = g_K[b];
    int row0 = rt * BM;
    if (row0 >= K) return;
    const float* W = g_wn + (size_t)(b * LL + l) * PP * DD;
    const int* clab = g_clab + b * PP;

    __shared__ float As[2][BKc][BM + 4];   /* stride 68, float4-aligned */
    __shared__ float Bs[2][BKc][BN + 4];   /* stride 132 */

    int tid = threadIdx.x;
    int tx = tid & 15, ty = tid >> 4;

    int rlab[8];
#pragma unroll
    for (int r = 0; r < 8; r++) rlab[r] = clab[row0 + ty * 8 + r];

    float mneg[8], ssum[8];
#pragma unroll
    for (int r = 0; r < 8; r++) { mneg[r] = -3.0e38f; ssum[r] = 0.f; }

    int nct = (K + BN - 1) / BN;

    auto load_stage = [&](int buf, int ks, int col0) {
#pragma unroll
        for (int j = 0; j < 2; j++) {
            int q = tid + j * 128;
            int ar = q >> 2, kq = (q & 3) * 4;
            float4 v = *(const float4*)(W + (size_t)(row0 + ar) * DD + ks + kq);
            As[buf][kq + 0][ar] = v.x; As[buf][kq + 1][ar] = v.y;
            As[buf][kq + 2][ar] = v.z; As[buf][kq + 3][ar] = v.w;
        }
#pragma unroll
        for (int j = 0; j < 4; j++) {
            int q = tid + j * 128;
            int bc = q >> 2, kq = (q & 3) * 4;
            float4 v = *(const float4*)(W + (size_t)(col0 + bc) * DD + ks + kq);
            Bs[buf][kq + 0][bc] = v.x; Bs[buf][kq + 1][bc] = v.y;
            Bs[buf][kq + 2][bc] = v.z; Bs[buf][kq + 3][bc] = v.w;
        }
    };

    for (int ct = 0; ct < nct; ct++) {
        int col0 = ct * BN;
        float acc[8][8];
#pragma unroll
        for (int r = 0; r < 8; r++)
#pragma unroll
            for (int c = 0; c < 8; c++) acc[r][c] = 0.f;

        load_stage(0, 0, col0);
        __syncthreads();
        int buf = 0;
#pragma unroll 1
        for (int s = 0; s < DD / BKc; s++) {
            if (s + 1 < DD / BKc) load_stage(buf ^ 1, (s + 1) * BKc, col0);
#pragma unroll
            for (int kk = 0; kk < BKc; kk++) {
                float a[8], bb[8];
                *(float4*)&a[0]  = *(const float4*)&As[buf][kk][ty * 8];
                *(float4*)&a[4]  = *(const float4*)&As[buf][kk][ty * 8 + 4];
                *(float4*)&bb[0] = *(const float4*)&Bs[buf][kk][tx * 8];
                *(float4*)&bb[4] = *(const float4*)&Bs[buf][kk][tx * 8 + 4];
#pragma unroll
                for (int r = 0; r < 8; r++)
#pragma unroll
                    for (int c = 0; c < 8; c++)
                        acc[r][c] = fmaf(a[r], bb[c], acc[r][c]);
            }
            __syncthreads();
            buf ^= 1;
        }

        /* masked logsumexp epilogue, fixed reference point M0 */
        int collab[8]; bool cvalid[8];
#pragma unroll
        for (int c = 0; c < 8; c++) {
            int col = col0 + tx * 8 + c;
            cvalid[c] = (col < K);
            collab[c] = clab[col];   /* pad cols hold -1, masked by cvalid */
        }
#pragma unroll
        for (int r = 0; r < 8; r++) {
            int lr = rlab[r];
#pragma unroll
            for (int c = 0; c < 8; c++) {
                float z = acc[r][c] * M0C;   /* /0.07 */
                bool isneg = cvalid[c] && (collab[c] != lr);
                float zz = isneg ? (z - M0C) : -40.0f;
                ssum[r] += fast_exp(zz);
                mneg[r] = fmaxf(mneg[r], isneg ? z : -3.0e38f);
            }
        }
    }

    /* reduce across the 16 tx lanes sharing each row */
#pragma unroll
    for (int r = 0; r < 8; r++) {
        float m = mneg[r], s = ssum[r];
#pragma unroll
        for (int off = 8; off; off >>= 1) {
            m = fmaxf(m, __shfl_xor_sync(0xffffffffu, m, off, 16));
            s += __shfl_xor_sync(0xffffffffu, s, off, 16);
        }
        int row = row0 + ty * 8 + r;
        if (tx == 0 && row < K) {
            size_t o = (size_t)(b * LL + l) * PP + row;
            g_maxneg[o] = m;
            g_S[o] = s;
        }
    }
}

/* ------------- K6: per-(b,l) loss reduction ------------- */
__global__ void k_final() {
    int bl = blockIdx.x; int b = bl / LL;
    int tid = threadIdx.x;
    int K = g_K[b];
    float acc = 0.f;
    for (int k = tid; k < K; k += blockDim.x) {
        size_t o = (size_t)bl * PP + k;
        float zp = g_zp[o], S = g_S[o], mn = g_maxneg[o];
        int negc = g_cnegcnt[b * PP + k];
        float m = fmaxf(zp, mn);
        float sum_neg = (negc > 0) ? S * expf(M0C - m) : 0.f;
        float padterm = 0.f;
        if (negc > 0) {
            int padi = K - 1 - negc; if (padi < 0) padi = 0;
            padterm = (float)padi * expf(g_zl[o] - m);
        }
        acc += m + logf(expf(zp - m) + sum_neg + padterm) - zp;
    }
    __shared__ float red[256];
    red[tid] = acc; __syncthreads();
    for (int s = 128; s; s >>= 1) {
        if (tid < s) red[tid] += red[tid + s];
        __syncthreads();
    }
    if (tid == 0) {
        int Kd = (K > 1) ? K : 1;
        g_partial[bl] = g_gate[b] ? (red[0] / (float)Kd) : 0.f;
    }
}

/* ------------- K7: final scalar ------------- */
__global__ void k_out(float* __restrict__ out) {
    __shared__ float red[64];
    int tid = threadIdx.x;
    red[tid] = (tid < BB * LL) ? g_partial[tid] : 0.f;
    __syncthreads();
    for (int s = 32; s; s >>= 1) {
        if (tid < s) red[tid] += red[tid + s];
        __syncthreads();
    }
    if (tid == 0) out[0] = red[0];
}

/* ------------------- launch ------------------- */
extern "C" void kernel_launch(void* const* d_in, const int* in_sizes, int n_in,
                              void* d_out, int out_size) {
    const float* meta = (const float*)d_in[0];
    const int* thing = (const int*)d_in[1];
    const int* label = (const int*)d_in[2];
    float* out = (float*)d_out;

    k_meta<<<BB, 256>>>(thing, label);
    k_norm<<<(BB * LL * PP) / 8, 256>>>(meta);        /* 1 warp per row */
    k_pick<<<(BLP + 255) / 256, 256>>>(label);
    k_zpzl<<<(BLP + 7) / 8, 256>>>();                 /* 1 warp per (b,l,k) */
    dim3 g5(PP / BM, LL, BB);
    k_lse<<<g5, 128>>>();
    k_final<<<BB * LL, 256>>>();
    k_out<<<1, 64>>>(out);
}

// round 3
// speedup vs baseline: 1.1302x; 1.1302x over previous
#include <cuda_runtime.h>
#include <cuda_bf16.h>
#include <stdint.h>

#define BB 8
#define NN 128
#define TT 8
#define LL 6
#define PP 1024
#define DD 256
#define NLABEL 40
#define BLP (BB*LL*PP)      /* 49152 */
#define M0C (1.0f/0.07f)

/* ------------- device scratch (no allocations allowed) ------------- */
__device__ uint4 g_wh4[(size_t)BB*LL*PP*DD/8];  /* bf16 normalized rows, 16B-aligned */
__device__ int   g_K[BB];
__device__ int   g_gate[BB];
__device__ int   g_comp2orig[BB*PP];
__device__ int   g_orig2comp[BB*PP];
__device__ int   g_clab[BB*PP];               /* labels by compact idx, pad=-1 */
__device__ int   g_cnegcnt[BB*PP];
__device__ int   g_poscnt_orig[BB*PP];
__device__ int   g_posingrp[BB*PP];
__device__ int   g_grpoff[BB*(NLABEL+1)];
__device__ int   g_grpitems[BB*PP];
__device__ int   g_idxlast_orig[BB*PP];       /* keyed by compact idx */
__device__ int   g_pospick[BLP];
__device__ float g_zp[BLP];
__device__ float g_zl[BLP];
__device__ float g_maxneg[BLP];
__device__ float g_S[BLP];
__device__ float g_partial[BB*LL];

/* ------------------- helpers ------------------- */
__device__ __forceinline__ uint32_t rotl32(uint32_t x, int r) {
    return (x << r) | (x >> (32 - r));
}

/* JAX threefry2x32 with key = jax.random.key(42) -> (0, 42) */
__device__ __forceinline__ void threefry_0_42(uint32_t& x0, uint32_t& x1) {
    const uint32_t ks0 = 0u, ks1 = 42u, ks2 = 0u ^ 42u ^ 0x1BD11BDAu;
    x0 += ks0; x1 += ks1;
#define TF_RND(r) { x0 += x1; x1 = rotl32(x1, r); x1 ^= x0; }
    TF_RND(13) TF_RND(15) TF_RND(26) TF_RND(6)  x0 += ks1; x1 += ks2 + 1u;
    TF_RND(17) TF_RND(29) TF_RND(16) TF_RND(24) x0 += ks2; x1 += ks0 + 2u;
    TF_RND(13) TF_RND(15) TF_RND(26) TF_RND(6)  x0 += ks0; x1 += ks1 + 3u;
    TF_RND(17) TF_RND(29) TF_RND(16) TF_RND(24) x0 += ks1; x1 += ks2 + 4u;
    TF_RND(13) TF_RND(15) TF_RND(26) TF_RND(6)  x0 += ks2; x1 += ks0 + 5u;
#undef TF_RND
}

/* FMA-pipe exp(x), x in [-60, 0.1]. Avoids MUFU throughput wall. */
__device__ __forceinline__ float fast_exp(float x) {
    float y = x * 1.4426950408889634f;
    int   n = __float2int_rn(y);
    float f = y - (float)n;
    float p = 1.3333558146e-3f;
    p = fmaf(p, f, 9.6181291076e-3f);
    p = fmaf(p, f, 5.5504108664e-2f);
    p = fmaf(p, f, 2.4022650695e-1f);
    p = fmaf(p, f, 6.9314718056e-1f);
    p = fmaf(p, f, 1.0f);
    return __int_as_float(__float_as_int(p) + (n << 23));
}

__device__ __forceinline__ void mma_bf16(float& d0, float& d1, float& d2, float& d3,
                                         uint32_t a0, uint32_t a1, uint32_t a2, uint32_t a3,
                                         uint32_t b0, uint32_t b1) {
    asm volatile(
        "mma.sync.aligned.m16n8k16.row.col.f32.bf16.bf16.f32 "
        "{%0,%1,%2,%3}, {%4,%5,%6,%7}, {%8,%9}, {%0,%1,%2,%3};"
        : "+f"(d0), "+f"(d1), "+f"(d2), "+f"(d3)
        : "r"(a0), "r"(a1), "r"(a2), "r"(a3), "r"(b0), "r"(b1));
}

/* ------------------- K1: per-batch metadata ------------------- */
__global__ void k_meta(const int* __restrict__ thing, const int* __restrict__ label) {
    int b = blockIdx.x, tid = threadIdx.x;
    __shared__ int s_pack[PP];          /* 0 = invalid, else label+1 */
    __shared__ int s_cnt[NLABEL];
    __shared__ int s_off[NLABEL + 1];
    __shared__ int s_L1, s_L2, s_labL1, s_gate, s_K;
    if (tid < NLABEL) s_cnt[tid] = 0;
    if (tid == 0) { s_L1 = -1; s_L2 = -1; s_gate = 0; }
    __syncthreads();
    for (int p = tid; p < PP; p += blockDim.x) {
        int v = thing[b * PP + p];
        int lab = label[b * PP + p];
        s_pack[p] = (v != 0) ? (lab + 1) : 0;
        if (v != 0) { atomicAdd(&s_cnt[lab], 1); atomicMax(&s_L1, p); }
    }
    for (int n = tid; n < NN; n += blockDim.x) {
        int ss = 0;
        for (int t = 0; t < TT; t++) ss += thing[(b * NN + n) * TT + t];
        if (ss > 0) atomicAdd(&s_gate, 1);
    }
    __syncthreads();
    if (tid == 0) {
        int acc = 0;
        for (int v = 0; v < NLABEL; v++) { s_off[v] = acc; acc += s_cnt[v]; }
        s_off[NLABEL] = acc; s_K = acc;
        g_K[b] = acc;
        g_gate[b] = (s_gate >= 2) ? 1 : 0;
        s_labL1 = (s_L1 >= 0) ? (s_pack[s_L1] - 1) : -1;
    }
    __syncthreads();
    int labL1 = s_labL1;
    for (int p = tid; p < PP; p += blockDim.x) {
        int pk = s_pack[p];
        if (pk != 0 && (pk - 1) != labL1) atomicMax(&s_L2, p);
    }
    __syncthreads();
    int K = s_K, L1 = s_L1, L2 = s_L2;
    for (int p = tid; p < PP; p += blockDim.x) {
        int pk = s_pack[p];
        if (pk == 0) { g_orig2comp[b * PP + p] = -1; continue; }
        int crank = 0, grank = 0;
        for (int q = 0; q < p; q++) {
            int qk = s_pack[q];
            crank += (qk != 0);
            grank += (qk == pk);
        }
        int lab = pk - 1;
        g_orig2comp[b * PP + p] = crank;
        g_comp2orig[b * PP + crank] = p;
        g_clab[b * PP + crank] = lab;
        int cl = s_cnt[lab];
        g_poscnt_orig[b * PP + p] = cl - 1;
        g_cnegcnt[b * PP + crank] = K - cl;
        g_posingrp[b * PP + p] = grank;
        g_grpitems[b * PP + s_off[lab] + grank] = p;
        g_idxlast_orig[b * PP + crank] = (lab != labL1) ? L1 : L2;
    }
    if (tid <= NLABEL) g_grpoff[b * (NLABEL + 1) + tid] = s_off[tid];
    /* pad region: deterministic sentinels */
    for (int k = tid; k < PP; k += blockDim.x)
        if (k >= K) {
            g_clab[b * PP + k] = -1;
            g_cnegcnt[b * PP + k] = 0;
            g_idxlast_orig[b * PP + k] = -1;
        }
}

/* ------------- K2: normalize rows -> bf16, compact layout [b][l][k][d] ------------- */
__global__ void k_norm(const float* __restrict__ meta) {
    int w = (blockIdx.x * blockDim.x + threadIdx.x) >> 5;
    int lane = threadIdx.x & 31;
    int b = w / (LL * PP); int rem = w % (LL * PP);
    int l = rem / PP; int k = rem % PP;
    size_t rowbase = ((size_t)(b * LL + l) * PP + k) * (DD / 8);
    int K = g_K[b];
    if (k >= K) {
        g_wh4[rowbase + lane] = make_uint4(0u, 0u, 0u, 0u);
        return;
    }
    int p = g_comp2orig[b * PP + k];
    int n = p >> 3, t = p & 7;
    const float* src = meta + ((((size_t)b * NN + n) * TT + t) * LL + l) * DD;
    float4 v0 = ((const float4*)src)[lane * 2];
    float4 v1 = ((const float4*)src)[lane * 2 + 1];
    float ss = v0.x*v0.x + v0.y*v0.y + v0.z*v0.z + v0.w*v0.w
             + v1.x*v1.x + v1.y*v1.y + v1.z*v1.z + v1.w*v1.w;
    for (int off = 16; off; off >>= 1) ss += __shfl_xor_sync(0xffffffffu, ss, off);
    float inv = 1.0f / fmaxf(sqrtf(ss), 1e-12f);
    v0.x*=inv; v0.y*=inv; v0.z*=inv; v0.w*=inv;
    v1.x*=inv; v1.y*=inv; v1.z*=inv; v1.w*=inv;
    __nv_bfloat162 h0 = __floats2bfloat162_rn(v0.x, v0.y);
    __nv_bfloat162 h1 = __floats2bfloat162_rn(v0.z, v0.w);
    __nv_bfloat162 h2 = __floats2bfloat162_rn(v1.x, v1.y);
    __nv_bfloat162 h3 = __floats2bfloat162_rn(v1.z, v1.w);
    uint4 o;
    o.x = *(uint32_t*)&h0; o.y = *(uint32_t*)&h1;
    o.z = *(uint32_t*)&h2; o.w = *(uint32_t*)&h3;
    g_wh4[rowbase + lane] = o;
}

/* ------------- K3: threefry (PARTITIONABLE mode) -> random positive pick ------------- */
__global__ void k_pick(const int* __restrict__ label) {
    int i = blockIdx.x * blockDim.x + threadIdx.x;
    if (i >= BLP) return;
    int b = i / (LL * PP); int rem = i % (LL * PP);
    int l = rem / PP; int p = rem % PP;
    int k = g_orig2comp[b * PP + p];
    if (k < 0) return;
    int pc = g_poscnt_orig[b * PP + p];
    int target;
    if (pc > 0) {
        uint32_t x0 = 0u, x1 = (uint32_t)i;
        threefry_0_42(x0, x1);
        uint32_t bits = x0 ^ x1;
        float u = __uint_as_float((bits >> 9) | 0x3F800000u) - 1.0f;
        int r = (int)floorf(u * (float)pc);
        if (r > pc - 1) r = pc - 1;
        if (r < 0) r = 0;
        int lab = label[b * PP + p];
        int start = g_grpoff[b * (NLABEL + 1) + lab];
        int j = g_posingrp[b * PP + p];
        int sel = (r < j) ? r : (r + 1);
        target = g_grpitems[b * PP + start + sel];
    } else {
        target = p;   /* diag fallback */
    }
    g_pospick[(b * LL + l) * PP + k] = g_orig2comp[b * PP + target];
}

/* ------------- K5: bf16 tensor-core GEMM + masked max / sum-exp + zp/zl ------------- */
#define BM 128
#define BN 128
#define BK 32
#define NST (DD / BK)   /* 8 */
#define PADK (BK + 8)   /* 80-byte rows: conflict-free b32 fragment reads */

__global__ __launch_bounds__(256) void k_lse_mma() {
    int b = blockIdx.z, l = blockIdx.y, rt = blockIdx.x;
    int K = g_K[b];
    int row0 = rt * BM;
    if (row0 >= K) return;
    int bl = b * LL + l;
    const __nv_bfloat16* W = (const __nv_bfloat16*)g_wh4 + (size_t)bl * PP * DD;
    const int* clab = g_clab + b * PP;

    __shared__ __align__(16) __nv_bfloat16 As[2][BM][PADK];
    __shared__ __align__(16) __nv_bfloat16 Bs[2][BM][PADK];
    __shared__ int scolab[BM];
    __shared__ int spick[BM], slast[BM];
    __shared__ float sm_m[2][4][64], sm_s[2][4][64];

    int tid = threadIdx.x;
    int wid = tid >> 5, lane = tid & 31;
    int mwarp = wid >> 2, nwarp = wid & 3;     /* 2 x 4 warp grid */
    int g = lane >> 2, tg = lane & 3;

    if (tid < BM) {
        int r = row0 + tid;
        spick[tid] = g_pospick[(size_t)bl * PP + r];
        int lo = g_idxlast_orig[b * PP + r];
        slast[tid] = (lo >= 0) ? g_orig2comp[b * PP + lo] : -2;
    }

    /* row labels for this thread's 8 rows */
    int rl[8];
#pragma unroll
    for (int mt = 0; mt < 4; mt++) {
        int rr = mwarp * 64 + mt * 16 + g;
        rl[mt * 2 + 0] = clab[row0 + rr];
        rl[mt * 2 + 1] = clab[row0 + rr + 8];
    }

    float mn8[8], ss8[8];
#pragma unroll
    for (int i = 0; i < 8; i++) { mn8[i] = -3.0e38f; ss8[i] = 0.f; }

    int nct = (K + BN - 1) / BN;

    for (int ct = 0; ct < nct; ct++) {
        int col0 = ct * BN;
        __syncthreads();   /* scolab from previous ct fully consumed */
        if (tid < BM) scolab[tid] = clab[col0 + tid];

        /* stage 0 load (direct) */
        {
#pragma unroll
            for (int j = 0; j < 2; j++) {
                int idx = tid + j * 256;
                int row = idx >> 2, seg = idx & 3;
                uint4 va = *(const uint4*)(W + (size_t)(row0 + row) * DD + seg * 8);
                uint4 vb = *(const uint4*)(W + (size_t)(col0 + row) * DD + seg * 8);
                *(uint4*)&As[0][row][seg * 8] = va;
                *(uint4*)&Bs[0][row][seg * 8] = vb;
            }
        }
        __syncthreads();

        float acc[4][4][4];
#pragma unroll
        for (int mt = 0; mt < 4; mt++)
#pragma unroll
            for (int nt = 0; nt < 4; nt++)
#pragma unroll
                for (int q = 0; q < 4; q++) acc[mt][nt][q] = 0.f;

        int buf = 0;
#pragma unroll 1
        for (int s = 0; s < NST; s++) {
            uint4 pa[2], pb[2];
            if (s + 1 < NST) {
                int ks = (s + 1) * BK;
#pragma unroll
                for (int j = 0; j < 2; j++) {
                    int idx = tid + j * 256;
                    int row = idx >> 2, seg = idx & 3;
                    pa[j] = *(const uint4*)(W + (size_t)(row0 + row) * DD + ks + seg * 8);
                    pb[j] = *(const uint4*)(W + (size_t)(col0 + row) * DD + ks + seg * 8);
                }
            }
#pragma unroll
            for (int kk = 0; kk < BK; kk += 16) {
                uint32_t bf[4][2];
#pragma unroll
                for (int nt = 0; nt < 4; nt++) {
                    int c = nwarp * 32 + nt * 8 + g;
                    bf[nt][0] = *(const uint32_t*)&Bs[buf][c][kk + tg * 2];
                    bf[nt][1] = *(const uint32_t*)&Bs[buf][c][kk + 8 + tg * 2];
                }
#pragma unroll
                for (int mt = 0; mt < 4; mt++) {
                    int r = mwarp * 64 + mt * 16 + g;
                    uint32_t a0 = *(const uint32_t*)&As[buf][r][kk + tg * 2];
                    uint32_t a1 = *(const uint32_t*)&As[buf][r + 8][kk + tg * 2];
                    uint32_t a2 = *(const uint32_t*)&As[buf][r][kk + 8 + tg * 2];
                    uint32_t a3 = *(const uint32_t*)&As[buf][r + 8][kk + 8 + tg * 2];
#pragma unroll
                    for (int nt = 0; nt < 4; nt++)
                        mma_bf16(acc[mt][nt][0], acc[mt][nt][1], acc[mt][nt][2], acc[mt][nt][3],
                                 a0, a1, a2, a3, bf[nt][0], bf[nt][1]);
                }
            }
            if (s + 1 < NST) {
#pragma unroll
                for (int j = 0; j < 2; j++) {
                    int idx = tid + j * 256;
                    int row = idx >> 2, seg = idx & 3;
                    *(uint4*)&As[buf ^ 1][row][seg * 8] = pa[j];
                    *(uint4*)&Bs[buf ^ 1][row][seg * 8] = pb[j];
                }
            }
            __syncthreads();
            buf ^= 1;
        }

        /* epilogue: masked lse accumulation + zp/zl capture */
#pragma unroll
        for (int mt = 0; mt < 4; mt++) {
#pragma unroll
            for (int e = 0; e < 2; e++) {
                int rloc = mwarp * 64 + mt * 16 + g + 8 * e;
                int lr = rl[mt * 2 + e];
                size_t o = (size_t)bl * PP + row0 + rloc;
#pragma unroll
                for (int nt = 0; nt < 4; nt++) {
                    int cbase = nwarp * 32 + nt * 8 + tg * 2;
#pragma unroll
                    for (int q = 0; q < 2; q++) {
                        float z = acc[mt][nt][e * 2 + q] * M0C;
                        int ctile = cbase + q;
                        int cl = scolab[ctile];
                        bool isneg = (cl >= 0) && (cl != lr);
                        if (isneg) {
                            ss8[mt * 2 + e] += fast_exp(z - M0C);
                            mn8[mt * 2 + e] = fmaxf(mn8[mt * 2 + e], z);
                        }
                        if (lr >= 0) {
                            int cglob = col0 + ctile;
                            if (cglob == spick[rloc]) g_zp[o] = z;
                            if (cglob == slast[rloc]) g_zl[o] = z;
                        }
                    }
                }
            }
        }
    }

    /* reduce across tg lanes (4 lanes share a row) */
#pragma unroll
    for (int i = 0; i < 8; i++) {
        float m = mn8[i], s = ss8[i];
        m = fmaxf(m, __shfl_xor_sync(0xffffffffu, m, 1));
        m = fmaxf(m, __shfl_xor_sync(0xffffffffu, m, 2));
        s += __shfl_xor_sync(0xffffffffu, s, 1);
        s += __shfl_xor_sync(0xffffffffu, s, 2);
        mn8[i] = m; ss8[i] = s;
    }
    if (tg == 0) {
#pragma unroll
        for (int mt = 0; mt < 4; mt++)
#pragma unroll
            for (int e = 0; e < 2; e++) {
                int r64 = mt * 16 + g + 8 * e;
                sm_m[mwarp][nwarp][r64] = mn8[mt * 2 + e];
                sm_s[mwarp][nwarp][r64] = ss8[mt * 2 + e];
            }
    }
    __syncthreads();
    if (tid < 128) {
        int mw = tid >> 6, r64 = tid & 63;
        float m = -3.0e38f, s = 0.f;
#pragma unroll
        for (int w = 0; w < 4; w++) {
            m = fmaxf(m, sm_m[mw][w][r64]);
            s += sm_s[mw][w][r64];
        }
        int rglob = row0 + mw * 64 + r64;
        if (rglob < K) {
            size_t o = (size_t)bl * PP + rglob;
            g_maxneg[o] = m;
            g_S[o] = s;
        }
    }
}

/* ------------- K6: per-(b,l) loss reduction ------------- */
__global__ void k_final() {
    int bl = blockIdx.x; int b = bl / LL;
    int tid = threadIdx.x;
    int K = g_K[b];
    float acc = 0.f;
    for (int k = tid; k < K; k += blockDim.x) {
        size_t o = (size_t)bl * PP + k;
        float zp = g_zp[o], S = g_S[o], mn = g_maxneg[o];
        int negc = g_cnegcnt[b * PP + k];
        float m = fmaxf(zp, mn);
        float sum_neg = (negc > 0) ? S * expf(M0C - m) : 0.f;
        float padterm = 0.f;
        if (negc > 0) {
            int padi = K - 1 - negc; if (padi < 0) padi = 0;
            padterm = (float)padi * expf(g_zl[o] - m);
        }
        acc += m + logf(expf(zp - m) + sum_neg + padterm) - zp;
    }
    __shared__ float red[256];
    red[tid] = acc; __syncthreads();
    for (int s = 128; s; s >>= 1) {
        if (tid < s) red[tid] += red[tid + s];
        __syncthreads();
    }
    if (tid == 0) {
        int Kd = (K > 1) ? K : 1;
        g_partial[bl] = g_gate[b] ? (red[0] / (float)Kd) : 0.f;
    }
}

/* ------------- K7: final scalar ------------- */
__global__ void k_out(float* __restrict__ out) {
    __shared__ float red[64];
    int tid = threadIdx.x;
    red[tid] = (tid < BB * LL) ? g_partial[tid] : 0.f;
    __syncthreads();
    for (int s = 32; s; s >>= 1) {
        if (tid < s) red[tid] += red[tid + s];
        __syncthreads();
    }
    if (tid == 0) out[0] = red[0];
}

/* ------------------- launch ------------------- */
extern "C" void kernel_launch(void* const* d_in, const int* in_sizes, int n_in,
                              void* d_out, int out_size) {
    const float* meta = (const float*)d_in[0];
    const int* thing = (const int*)d_in[1];
    const int* label = (const int*)d_in[2];
    float* out = (float*)d_out;

    k_meta<<<BB, 256>>>(thing, label);
    k_norm<<<(BB * LL * PP) / 8, 256>>>(meta);        /* 1 warp per row */
    k_pick<<<(BLP + 255) / 256, 256>>>(label);
    dim3 g5(PP / BM, LL, BB);
    k_lse_mma<<<g5, 256>>>();
    k_final<<<BB * LL, 256>>>();
    k_out<<<1, 64>>>(out);
}

// round 6
// speedup vs baseline: 2.9491x; 2.6095x over previous
#include <cuda_runtime.h>
#include <cuda_bf16.h>
#include <stdint.h>

#define BB 8
#define NN 128
#define TT 8
#define LL 6
#define PP 1024
#define DD 256
#define NLABEL 40
#define BLP (BB*LL*PP)      /* 49152 */
#define M0C (1.0f/0.07f)
#define C2LOG (20.609929155556620f)   /* M0C * log2(e) */

/* ------------- device scratch (no allocations allowed) ------------- */
__device__ uint4 g_wh4[(size_t)BB*LL*PP*DD/8];  /* bf16 normalized rows */
__device__ int   g_K[BB];
__device__ int   g_gate[BB];
__device__ int   g_comp2orig[BB*PP];
__device__ int   g_orig2comp[BB*PP];
__device__ __align__(16) int g_clab[BB*PP];   /* labels by compact idx, pad=-1 */
__device__ int   g_cnegcnt[BB*PP];
__device__ int   g_poscnt_orig[BB*PP];
__device__ int   g_posingrp[BB*PP];
__device__ int   g_grpoff[BB*(NLABEL+1)];
__device__ int   g_grpitems[BB*PP];
__device__ int   g_idxlast_orig[BB*PP];       /* keyed by compact idx */
__device__ int   g_pospick[BLP];
__device__ float g_zp[BLP];
__device__ float g_zl[BLP];
__device__ float g_S[BLP];
__device__ float g_partial[BB*LL];

/* ------------------- helpers ------------------- */
__device__ __forceinline__ uint32_t rotl32(uint32_t x, int r) {
    return (x << r) | (x >> (32 - r));
}

/* JAX threefry2x32 with key = jax.random.key(42) -> (0, 42) */
__device__ __forceinline__ void threefry_0_42(uint32_t& x0, uint32_t& x1) {
    const uint32_t ks0 = 0u, ks1 = 42u, ks2 = 0u ^ 42u ^ 0x1BD11BDAu;
    x0 += ks0; x1 += ks1;
#define TF_RND(r) { x0 += x1; x1 = rotl32(x1, r); x1 ^= x0; }
    TF_RND(13) TF_RND(15) TF_RND(26) TF_RND(6)  x0 += ks1; x1 += ks2 + 1u;
    TF_RND(17) TF_RND(29) TF_RND(16) TF_RND(24) x0 += ks2; x1 += ks0 + 2u;
    TF_RND(13) TF_RND(15) TF_RND(26) TF_RND(6)  x0 += ks0; x1 += ks1 + 3u;
    TF_RND(17) TF_RND(29) TF_RND(16) TF_RND(24) x0 += ks1; x1 += ks2 + 4u;
    TF_RND(13) TF_RND(15) TF_RND(26) TF_RND(6)  x0 += ks2; x1 += ks0 + 5u;
#undef TF_RND
}

/* exp2(y) on FMA pipe, y in [-110, 0.5] */
__device__ __forceinline__ float exp2_poly(float y) {
    int   n = __float2int_rn(y);
    float f = y - (float)n;
    float p = 1.3333558146e-3f;
    p = fmaf(p, f, 9.6181291076e-3f);
    p = fmaf(p, f, 5.5504108664e-2f);
    p = fmaf(p, f, 2.4022650695e-1f);
    p = fmaf(p, f, 6.9314718056e-1f);
    p = fmaf(p, f, 1.0f);
    return __int_as_float(__float_as_int(p) + (n << 23));
}

__device__ __forceinline__ void mma_bf16(float& d0, float& d1, float& d2, float& d3,
                                         uint32_t a0, uint32_t a1, uint32_t a2, uint32_t a3,
                                         uint32_t b0, uint32_t b1) {
    asm volatile(
        "mma.sync.aligned.m16n8k16.row.col.f32.bf16.bf16.f32 "
        "{%0,%1,%2,%3}, {%4,%5,%6,%7}, {%8,%9}, {%0,%1,%2,%3};"
        : "+f"(d0), "+f"(d1), "+f"(d2), "+f"(d3)
        : "r"(a0), "r"(a1), "r"(a2), "r"(a3), "r"(b0), "r"(b1));
}

#define LDSM4(r0, r1, r2, r3, addr) \
    asm volatile("ldmatrix.sync.aligned.m8n8.x4.shared.b16 {%0,%1,%2,%3}, [%4];" \
                 : "=r"(r0), "=r"(r1), "=r"(r2), "=r"(r3) : "r"(addr))

__device__ __forceinline__ void cp16(uint32_t dst, const void* src) {
    asm volatile("cp.async.cg.shared.global [%0], [%1], 16;" :: "r"(dst), "l"(src) : "memory");
}
#define CP_COMMIT() asm volatile("cp.async.commit_group;" ::: "memory")
#define CP_WAIT1()  asm volatile("cp.async.wait_group 1;" ::: "memory")

__device__ __forceinline__ uint32_t smem_u32(const void* p) {
    uint32_t a;
    asm("{ .reg .u64 t; cvta.to.shared.u64 t, %1; cvt.u32.u64 %0, t; }" : "=r"(a) : "l"(p));
    return a;
}

/* ------------------- K1: per-batch metadata ------------------- */
__global__ void k_meta(const int* __restrict__ thing, const int* __restrict__ label) {
    int b = blockIdx.x, tid = threadIdx.x;
    __shared__ int s_pack[PP];          /* 0 = invalid, else label+1 */
    __shared__ int s_cnt[NLABEL];
    __shared__ int s_off[NLABEL + 1];
    __shared__ int s_L1, s_L2, s_labL1, s_gate, s_K;
    if (tid < NLABEL) s_cnt[tid] = 0;
    if (tid == 0) { s_L1 = -1; s_L2 = -1; s_gate = 0; }
    __syncthreads();
    for (int p = tid; p < PP; p += blockDim.x) {
        int v = thing[b * PP + p];
        int lab = label[b * PP + p];
        s_pack[p] = (v != 0) ? (lab + 1) : 0;
        if (v != 0) { atomicAdd(&s_cnt[lab], 1); atomicMax(&s_L1, p); }
    }
    for (int n = tid; n < NN; n += blockDim.x) {
        int ss = 0;
        for (int t = 0; t < TT; t++) ss += thing[(b * NN + n) * TT + t];
        if (ss > 0) atomicAdd(&s_gate, 1);
    }
    __syncthreads();
    if (tid == 0) {
        int acc = 0;
        for (int v = 0; v < NLABEL; v++) { s_off[v] = acc; acc += s_cnt[v]; }
        s_off[NLABEL] = acc; s_K = acc;
        g_K[b] = acc;
        g_gate[b] = (s_gate >= 2) ? 1 : 0;
        s_labL1 = (s_L1 >= 0) ? (s_pack[s_L1] - 1) : -1;
    }
    __syncthreads();
    int labL1 = s_labL1;
    for (int p = tid; p < PP; p += blockDim.x) {
        int pk = s_pack[p];
        if (pk != 0 && (pk - 1) != labL1) atomicMax(&s_L2, p);
    }
    __syncthreads();
    int K = s_K, L1 = s_L1, L2 = s_L2;
    for (int p = tid; p < PP; p += blockDim.x) {
        int pk = s_pack[p];
        if (pk == 0) { g_orig2comp[b * PP + p] = -1; continue; }
        int crank = 0, grank = 0;
        for (int q = 0; q < p; q++) {
            int qk = s_pack[q];
            crank += (qk != 0);
            grank += (qk == pk);
        }
        int lab = pk - 1;
        g_orig2comp[b * PP + p] = crank;
        g_comp2orig[b * PP + crank] = p;
        g_clab[b * PP + crank] = lab;
        int cl = s_cnt[lab];
        g_poscnt_orig[b * PP + p] = cl - 1;
        g_cnegcnt[b * PP + crank] = K - cl;
        g_posingrp[b * PP + p] = grank;
        g_grpitems[b * PP + s_off[lab] + grank] = p;
        g_idxlast_orig[b * PP + crank] = (lab != labL1) ? L1 : L2;
    }
    if (tid <= NLABEL) g_grpoff[b * (NLABEL + 1) + tid] = s_off[tid];
    /* pad region: deterministic sentinels */
    for (int k = tid; k < PP; k += blockDim.x)
        if (k >= K) {
            g_clab[b * PP + k] = -1;
            g_cnegcnt[b * PP + k] = 0;
            g_idxlast_orig[b * PP + k] = -1;
        }
}

/* ------------- K2: normalize rows -> bf16, compact layout [b][l][k][d] ------------- */
__global__ void k_norm(const float* __restrict__ meta) {
    int w = (blockIdx.x * blockDim.x + threadIdx.x) >> 5;
    int lane = threadIdx.x & 31;
    int b = w / (LL * PP); int rem = w % (LL * PP);
    int l = rem / PP; int k = rem % PP;
    size_t rowbase = ((size_t)(b * LL + l) * PP + k) * (DD / 8);
    int K = g_K[b];
    if (k >= K) {
        g_wh4[rowbase + lane] = make_uint4(0u, 0u, 0u, 0u);
        return;
    }
    int p = g_comp2orig[b * PP + k];
    int n = p >> 3, t = p & 7;
    const float* src = meta + ((((size_t)b * NN + n) * TT + t) * LL + l) * DD;
    float4 v0 = ((const float4*)src)[lane * 2];
    float4 v1 = ((const float4*)src)[lane * 2 + 1];
    float ss = v0.x*v0.x + v0.y*v0.y + v0.z*v0.z + v0.w*v0.w
             + v1.x*v1.x + v1.y*v1.y + v1.z*v1.z + v1.w*v1.w;
    for (int off = 16; off; off >>= 1) ss += __shfl_xor_sync(0xffffffffu, ss, off);
    float inv = 1.0f / fmaxf(sqrtf(ss), 1e-12f);
    v0.x*=inv; v0.y*=inv; v0.z*=inv; v0.w*=inv;
    v1.x*=inv; v1.y*=inv; v1.z*=inv; v1.w*=inv;
    __nv_bfloat162 h0 = __floats2bfloat162_rn(v0.x, v0.y);
    __nv_bfloat162 h1 = __floats2bfloat162_rn(v0.z, v0.w);
    __nv_bfloat162 h2 = __floats2bfloat162_rn(v1.x, v1.y);
    __nv_bfloat162 h3 = __floats2bfloat162_rn(v1.z, v1.w);
    uint4 o;
    o.x = *(uint32_t*)&h0; o.y = *(uint32_t*)&h1;
    o.z = *(uint32_t*)&h2; o.w = *(uint32_t*)&h3;
    g_wh4[rowbase + lane] = o;
}

/* ------------- K3: threefry (PARTITIONABLE mode) -> random positive pick ------------- */
__global__ void k_pick(const int* __restrict__ label) {
    int i = blockIdx.x * blockDim.x + threadIdx.x;
    if (i >= BLP) return;
    int b = i / (LL * PP); int rem = i % (LL * PP);
    int l = rem / PP; int p = rem % PP;
    int k = g_orig2comp[b * PP + p];
    if (k < 0) return;
    int pc = g_poscnt_orig[b * PP + p];
    int target;
    if (pc > 0) {
        uint32_t x0 = 0u, x1 = (uint32_t)i;
        threefry_0_42(x0, x1);
        uint32_t bits = x0 ^ x1;
        float u = __uint_as_float((bits >> 9) | 0x3F800000u) - 1.0f;
        int r = (int)floorf(u * (float)pc);
        if (r > pc - 1) r = pc - 1;
        if (r < 0) r = 0;
        int lab = label[b * PP + p];
        int start = g_grpoff[b * (NLABEL + 1) + lab];
        int j = g_posingrp[b * PP + p];
        int sel = (r < j) ? r : (r + 1);
        target = g_grpitems[b * PP + start + sel];
    } else {
        target = p;   /* diag fallback */
    }
    g_pospick[(b * LL + l) * PP + k] = g_orig2comp[b * PP + target];
}

/* ------------- K5: HMMA (mma.sync bf16) GEMM + masked sum-exp + zp/zl -------------
 * CTA: 256 threads, 8 warps in 2x4 grid. Tile BM=64 x BN=128, BK=32.
 * Warp tile 32x32. A tile (64x256, 32KB) resident; B streamed, 3-stage cp.async.
 * ldmatrix.x4 with XOR-swizzled smem. LSE fixed reference point M0.
 * Per-row S reduced across tg lanes AND across the 4 nwarp warps (smem).
 */
#define BN_T 128
#define A_OFF    0        /* 8 stages x 4096 = 32768 */
#define B_OFF    32768    /* 3 bufs x 8192 = 24576 */
#define SLAB_OFF 57344    /* 2 x 512 label staging; reused for S reduction */
#define SMEM_DYN (58368 + 1024)

__device__ __forceinline__ void prefetch_stage(int gidx, int nstages,
                                               const __nv_bfloat16* __restrict__ W,
                                               const int* __restrict__ clab,
                                               uint32_t sb, int tid) {
    if (gidx < nstages) {
        int ct2 = gidx >> 3, s2 = gidx & 7;
        uint32_t bbase = sb + B_OFF + (uint32_t)(gidx % 3) * 8192u;
#pragma unroll
        for (int j = 0; j < 2; j++) {
            int id = j * 256 + tid;
            int r = id >> 2, c = id & 3;
            const void* src = W + (size_t)(ct2 * BN_T + r) * DD + s2 * 32 + c * 8;
            uint32_t dst = bbase + (uint32_t)(r * 64) + (uint32_t)((c ^ ((r >> 1) & 3)) << 4);
            cp16(dst, src);
        }
        if (s2 == 0 && tid < 32) {
            const void* src = clab + ct2 * 128 + tid * 4;
            cp16(sb + SLAB_OFF + (uint32_t)((ct2 & 1) * 512 + tid * 16), src);
        }
    }
    CP_COMMIT();
}

__global__ void __launch_bounds__(256, 2) k_lse_hmma() {
    extern __shared__ char dsm[];
    int b = blockIdx.z, l = blockIdx.y, rt = blockIdx.x;
    int K = g_K[b];
    int row0 = rt * 64;
    if (row0 >= K) return;
    int bl = b * LL + l;
    const __nv_bfloat16* W = (const __nv_bfloat16*)g_wh4 + (size_t)bl * PP * DD;
    const int* clab = g_clab + b * PP;

    uint32_t sraw = smem_u32(dsm);
    uint32_t sb = (sraw + 1023u) & ~1023u;
    char* amem = dsm + (sb - sraw);

    int tid = threadIdx.x;
    int wid = tid >> 5, lane = tid & 31;
    int mwarp = wid >> 2, nwarp = wid & 3;
    int g = lane >> 2, tg = lane & 3;
    int grp = lane >> 3, li = lane & 7;

    int nct = (K + 127) >> 7;
    int nstages = nct * 8;

    /* per-thread row state (4 rows: mt in {0,1}, e in {0,1}) */
    int rloc[4], rlab[4], pick[4], last[4];
    float ssum[4];
#pragma unroll
    for (int i = 0; i < 4; i++) {
        int mt = i >> 1, e = i & 1;
        rloc[i] = mwarp * 32 + mt * 16 + g + 8 * e;
        int grow = row0 + rloc[i];
        rlab[i] = clab[grow];
        pick[i] = g_pospick[(size_t)bl * PP + grow];
        int lo = g_idxlast_orig[b * PP + grow];
        last[i] = (lo >= 0) ? g_orig2comp[b * PP + lo] : -2;
        ssum[i] = 0.f;
    }

    /* fragment smem addresses */
    uint32_t rowA = (uint32_t)(mwarp * 32 + (grp & 1) * 8 + li);
    uint32_t cA = (uint32_t)(grp >> 1);
    uint32_t addrA0 = sb + A_OFF + rowA * 64u + ((cA ^ ((rowA >> 1) & 3u)) << 4);
    uint32_t rowB = (uint32_t)(nwarp * 32 + (grp >> 1) * 8 + li);
    uint32_t cB = (uint32_t)(grp & 1);
    uint32_t addrB0 = rowB * 64u + ((cB ^ ((rowB >> 1) & 3u)) << 4);

    /* prologue: A (whole 64x256) in group 0 + B stage 0 (group 0), stage 1 (group 1) */
#pragma unroll
    for (int j = 0; j < 8; j++) {
        int id = j * 256 + tid;
        int s = id >> 8, rem = id & 255;
        int r = rem >> 2, c = rem & 3;
        const void* src = W + (size_t)(row0 + r) * DD + s * 32 + c * 8;
        uint32_t dst = sb + A_OFF + (uint32_t)(s * 4096 + r * 64)
                     + (uint32_t)((c ^ ((r >> 1) & 3)) << 4);
        cp16(dst, src);
    }
    prefetch_stage(0, nstages, W, clab, sb, tid);
    prefetch_stage(1, nstages, W, clab, sb, tid);

    float acc[2][4][4];
#pragma unroll
    for (int mt = 0; mt < 2; mt++)
#pragma unroll
        for (int nt = 0; nt < 4; nt++)
#pragma unroll
            for (int q = 0; q < 4; q++) acc[mt][nt][q] = 0.f;

    for (int ct = 0; ct < nct; ct++) {
        int col0 = ct * BN_T;
#pragma unroll 1
        for (int s = 0; s < 8; s++) {
            int gi = ct * 8 + s;
            CP_WAIT1();
            __syncthreads();
            prefetch_stage(gi + 2, nstages, W, clab, sb, tid);

            uint32_t aAddr = addrA0 + (uint32_t)(s * 4096);
            uint32_t bAddr = sb + B_OFF + (uint32_t)((gi % 3) * 8192) + addrB0;
#pragma unroll
            for (int kk = 0; kk < 2; kk++) {
                uint32_t kx = (uint32_t)(kk * 32);
                uint32_t a0[4], a1[4], bf[8];
                LDSM4(a0[0], a0[1], a0[2], a0[3], aAddr ^ kx);
                LDSM4(a1[0], a1[1], a1[2], a1[3], (aAddr + 1024u) ^ kx);
                LDSM4(bf[0], bf[1], bf[2], bf[3], bAddr ^ kx);
                LDSM4(bf[4], bf[5], bf[6], bf[7], (bAddr + 1024u) ^ kx);
#pragma unroll
                for (int nt = 0; nt < 4; nt++) {
                    mma_bf16(acc[0][nt][0], acc[0][nt][1], acc[0][nt][2], acc[0][nt][3],
                             a0[0], a0[1], a0[2], a0[3], bf[nt * 2], bf[nt * 2 + 1]);
                    mma_bf16(acc[1][nt][0], acc[1][nt][1], acc[1][nt][2], acc[1][nt][3],
                             a1[0], a1[1], a1[2], a1[3], bf[nt * 2], bf[nt * 2 + 1]);
                }
            }
        }

        /* ---- epilogue for this 64x128 tile ---- */
        const int* slabp = (const int*)(amem + SLAB_OFF + (ct & 1) * 512);
        int cls[8];
#pragma unroll
        for (int nt = 0; nt < 4; nt++)
#pragma unroll
            for (int q = 0; q < 2; q++)
                cls[nt * 2 + q] = slabp[nwarp * 32 + nt * 8 + tg * 2 + q];

#pragma unroll
        for (int i = 0; i < 4; i++) {
            int mt = i >> 1, e = i & 1;
            int lr = rlab[i];
            size_t o = (size_t)bl * PP + row0 + rloc[i];
            float s4 = 0.f;
#pragma unroll
            for (int nt = 0; nt < 4; nt++) {
#pragma unroll
                for (int q = 0; q < 2; q++) {
                    float av = acc[mt][nt][e * 2 + q];
                    int cl = cls[nt * 2 + q];
                    bool isneg = (cl >= 0) && (cl != lr);
                    float y = fmaf(av, C2LOG, -C2LOG);
                    y = isneg ? y : -110.0f;
                    s4 += exp2_poly(y);
                    int cg = col0 + nwarp * 32 + nt * 8 + tg * 2 + q;
                    if (cg == pick[i]) g_zp[o] = av * M0C;
                    if (cg == last[i]) g_zl[o] = av * M0C;
                }
            }
            ssum[i] += s4;
        }
#pragma unroll
        for (int mt = 0; mt < 2; mt++)
#pragma unroll
            for (int nt = 0; nt < 4; nt++)
#pragma unroll
                for (int q = 0; q < 4; q++) acc[mt][nt][q] = 0.f;
    }

    /* ---- writeback: reduce tg lanes, then across the 4 nwarp warps ---- */
    __syncthreads();                      /* slab label reads all done */
    float* sred = (float*)(amem + SLAB_OFF);   /* 8 warps x 32 rows */
#pragma unroll
    for (int i = 0; i < 4; i++) {
        float s = ssum[i];
        s += __shfl_xor_sync(0xffffffffu, s, 1);
        s += __shfl_xor_sync(0xffffffffu, s, 2);
        if (tg == 0) {
            int mt = i >> 1, e = i & 1;
            sred[wid * 32 + mt * 16 + g + 8 * e] = s;
        }
    }
    __syncthreads();
    if (tid < 64) {
        int mw = tid >> 5, r32 = tid & 31;
        float s = sred[(mw * 4 + 0) * 32 + r32] + sred[(mw * 4 + 1) * 32 + r32]
                + sred[(mw * 4 + 2) * 32 + r32] + sred[(mw * 4 + 3) * 32 + r32];
        int grow = row0 + tid;
        if (grow < K)
            g_S[(size_t)bl * PP + grow] = s;
    }
}

/* ------------- K6: per-(b,l) loss reduction (fixed ref point M0) ------------- */
__global__ void k_final() {
    int bl = blockIdx.x; int b = bl / LL;
    int tid = threadIdx.x;
    int K = g_K[b];
    float acc = 0.f;
    for (int k = tid; k < K; k += blockDim.x) {
        size_t o = (size_t)bl * PP + k;
        float zp = g_zp[o], S = g_S[o];
        int negc = g_cnegcnt[b * PP + k];
        float ez = expf(zp - M0C);
        float padterm = 0.f;
        if (negc > 0) {
            int padi = K - 1 - negc; if (padi < 0) padi = 0;
            padterm = (float)padi * expf(g_zl[o] - M0C);
        } else {
            S = 0.f;
        }
        acc += M0C + logf(ez + S + padterm) - zp;
    }
    __shared__ float red[256];
    red[tid] = acc; __syncthreads();
    for (int s = 128; s; s >>= 1) {
        if (tid < s) red[tid] += red[tid + s];
        __syncthreads();
    }
    if (tid == 0) {
        int Kd = (K > 1) ? K : 1;
        g_partial[bl] = g_gate[b] ? (red[0] / (float)Kd) : 0.f;
    }
}

/* ------------- K7: final scalar ------------- */
__global__ void k_out(float* __restrict__ out) {
    __shared__ float red[64];
    int tid = threadIdx.x;
    red[tid] = (tid < BB * LL) ? g_partial[tid] : 0.f;
    __syncthreads();
    for (int s = 32; s; s >>= 1) {
        if (tid < s) red[tid] += red[tid + s];
        __syncthreads();
    }
    if (tid == 0) out[0] = red[0];
}

/* ------------------- launch ------------------- */
extern "C" void kernel_launch(void* const* d_in, const int* in_sizes, int n_in,
                              void* d_out, int out_size) {
    const float* meta = (const float*)d_in[0];
    const int* thing = (const int*)d_in[1];
    const int* label = (const int*)d_in[2];
    float* out = (float*)d_out;

    cudaFuncSetAttribute(k_lse_hmma, cudaFuncAttributeMaxDynamicSharedMemorySize, SMEM_DYN);

    k_meta<<<BB, 256>>>(thing, label);
    k_norm<<<(BB * LL * PP) / 8, 256>>>(meta);        /* 1 warp per row */
    k_pick<<<(BLP + 255) / 256, 256>>>(label);
    dim3 g5(PP / 64, LL, BB);
    k_lse_hmma<<<g5, 256, SMEM_DYN>>>();
    k_final<<<BB * LL, 256>>>();
    k_out<<<1, 64>>>(out);
}

// round 7
// speedup vs baseline: 3.9935x; 1.3541x over previous
#include <cuda_runtime.h>
#include <cuda_bf16.h>
#include <stdint.h>

#define BB 8
#define NN 128
#define TT 8
#define LL 6
#define PP 1024
#define DD 256
#define NLABEL 40
#define BLP (BB*LL*PP)      /* 49152 */
#define M0C (1.0f/0.07f)
#define C2LOG (20.609929155556620f)   /* M0C * log2(e) */

/* ------------- device scratch (no allocations allowed) ------------- */
__device__ uint4 g_wh4[(size_t)BB*LL*PP*DD/8];  /* bf16 normalized rows */
__device__ int   g_K[BB];
__device__ int   g_gate[BB];
__device__ int   g_comp2orig[BB*PP];
__device__ int   g_orig2comp[BB*PP];
__device__ __align__(16) int g_clab[BB*PP];   /* labels by compact idx, pad=-1 */
__device__ int   g_cnegcnt[BB*PP];
__device__ int   g_poscnt_orig[BB*PP];
__device__ int   g_posingrp[BB*PP];
__device__ int   g_grpoff[BB*(NLABEL+1)];
__device__ int   g_grpitems[BB*PP];
__device__ int   g_idxlast_orig[BB*PP];       /* keyed by compact idx */
__device__ int   g_pospick[BLP];
__device__ float g_zp[BLP];
__device__ float g_zl[BLP];
__device__ float g_S[BLP];
__device__ float g_partial[BB*LL];

/* ------------------- helpers ------------------- */
__device__ __forceinline__ uint32_t rotl32(uint32_t x, int r) {
    return (x << r) | (x >> (32 - r));
}

/* JAX threefry2x32 with key = jax.random.key(42) -> (0, 42) */
__device__ __forceinline__ void threefry_0_42(uint32_t& x0, uint32_t& x1) {
    const uint32_t ks0 = 0u, ks1 = 42u, ks2 = 0u ^ 42u ^ 0x1BD11BDAu;
    x0 += ks0; x1 += ks1;
#define TF_RND(r) { x0 += x1; x1 = rotl32(x1, r); x1 ^= x0; }
    TF_RND(13) TF_RND(15) TF_RND(26) TF_RND(6)  x0 += ks1; x1 += ks2 + 1u;
    TF_RND(17) TF_RND(29) TF_RND(16) TF_RND(24) x0 += ks2; x1 += ks0 + 2u;
    TF_RND(13) TF_RND(15) TF_RND(26) TF_RND(6)  x0 += ks0; x1 += ks1 + 3u;
    TF_RND(17) TF_RND(29) TF_RND(16) TF_RND(24) x0 += ks1; x1 += ks2 + 4u;
    TF_RND(13) TF_RND(15) TF_RND(26) TF_RND(6)  x0 += ks2; x1 += ks0 + 5u;
#undef TF_RND
}

/* exp2(y) on FMA pipe, y in [-110, 0.5] */
__device__ __forceinline__ float exp2_poly(float y) {
    int   n = __float2int_rn(y);
    float f = y - (float)n;
    float p = 1.3333558146e-3f;
    p = fmaf(p, f, 9.6181291076e-3f);
    p = fmaf(p, f, 5.5504108664e-2f);
    p = fmaf(p, f, 2.4022650695e-1f);
    p = fmaf(p, f, 6.9314718056e-1f);
    p = fmaf(p, f, 1.0f);
    return __int_as_float(__float_as_int(p) + (n << 23));
}

__device__ __forceinline__ void mma_bf16(float& d0, float& d1, float& d2, float& d3,
                                         uint32_t a0, uint32_t a1, uint32_t a2, uint32_t a3,
                                         uint32_t b0, uint32_t b1) {
    asm volatile(
        "mma.sync.aligned.m16n8k16.row.col.f32.bf16.bf16.f32 "
        "{%0,%1,%2,%3}, {%4,%5,%6,%7}, {%8,%9}, {%0,%1,%2,%3};"
        : "+f"(d0), "+f"(d1), "+f"(d2), "+f"(d3)
        : "r"(a0), "r"(a1), "r"(a2), "r"(a3), "r"(b0), "r"(b1));
}

#define LDSM4(r0, r1, r2, r3, addr) \
    asm volatile("ldmatrix.sync.aligned.m8n8.x4.shared.b16 {%0,%1,%2,%3}, [%4];" \
                 : "=r"(r0), "=r"(r1), "=r"(r2), "=r"(r3) : "r"(addr))

__device__ __forceinline__ void cp16(uint32_t dst, const void* src) {
    asm volatile("cp.async.cg.shared.global [%0], [%1], 16;" :: "r"(dst), "l"(src) : "memory");
}
#define CP_COMMIT() asm volatile("cp.async.commit_group;" ::: "memory")
#define CP_WAIT1()  asm volatile("cp.async.wait_group 1;" ::: "memory")

__device__ __forceinline__ uint32_t smem_u32(const void* p) {
    uint32_t a;
    asm("{ .reg .u64 t; cvta.to.shared.u64 t, %1; cvt.u32.u64 %0, t; }" : "=r"(a) : "l"(p));
    return a;
}

/* ------------------- K1: per-batch metadata (chunked rank scan) ------------------- */
__global__ void k_meta(const int* __restrict__ thing, const int* __restrict__ label) {
    int b = blockIdx.x, tid = threadIdx.x;
    __shared__ int s_pack[PP];          /* 0 = invalid, else label+1 */
    __shared__ int s_cnt[NLABEL];
    __shared__ int s_off[NLABEL + 1];
    __shared__ int s_run[NLABEL];
    __shared__ int s_chcnt[NLABEL];
    __shared__ int s_L1, s_L2, s_labL1, s_gate, s_K, s_crun, s_chval;
    if (tid < NLABEL) { s_cnt[tid] = 0; s_run[tid] = 0; }
    if (tid == 0) { s_L1 = -1; s_L2 = -1; s_gate = 0; s_crun = 0; }
    __syncthreads();
    for (int p = tid; p < PP; p += blockDim.x) {
        int v = thing[b * PP + p];
        int lab = label[b * PP + p];
        s_pack[p] = (v != 0) ? (lab + 1) : 0;
        if (v != 0) { atomicAdd(&s_cnt[lab], 1); atomicMax(&s_L1, p); }
    }
    for (int n = tid; n < NN; n += blockDim.x) {
        int ss = 0;
        for (int t = 0; t < TT; t++) ss += thing[(b * NN + n) * TT + t];
        if (ss > 0) atomicAdd(&s_gate, 1);
    }
    __syncthreads();
    if (tid == 0) {
        int acc = 0;
        for (int v = 0; v < NLABEL; v++) { s_off[v] = acc; acc += s_cnt[v]; }
        s_off[NLABEL] = acc; s_K = acc;
        g_K[b] = acc;
        g_gate[b] = (s_gate >= 2) ? 1 : 0;
        s_labL1 = (s_L1 >= 0) ? (s_pack[s_L1] - 1) : -1;
    }
    __syncthreads();
    int labL1 = s_labL1;
    for (int p = tid; p < PP; p += blockDim.x) {
        int pk = s_pack[p];
        if (pk != 0 && (pk - 1) != labL1) atomicMax(&s_L2, p);
    }
    __syncthreads();
    int K = s_K, L1 = s_L1, L2 = s_L2;

    /* ranks via 4 sequential chunks of 256 with running prefixes */
    for (int c = 0; c < 4; c++) {
        int base = c * 256;
        int p = base + tid;
        int pk = s_pack[p];
        int crloc = 0, grloc = 0;
        for (int q = base; q < p; q++) {
            int qk = s_pack[q];
            crloc += (qk != 0);
            grloc += (qk == pk);
        }
        if (pk == 0) {
            g_orig2comp[b * PP + p] = -1;
        } else {
            int lab = pk - 1;
            int crank = s_crun + crloc;
            int grank = s_run[lab] + grloc;
            g_orig2comp[b * PP + p] = crank;
            g_comp2orig[b * PP + crank] = p;
            g_clab[b * PP + crank] = lab;
            int cl = s_cnt[lab];
            g_poscnt_orig[b * PP + p] = cl - 1;
            g_cnegcnt[b * PP + crank] = K - cl;
            g_posingrp[b * PP + p] = grank;
            g_grpitems[b * PP + s_off[lab] + grank] = p;
            g_idxlast_orig[b * PP + crank] = (lab != labL1) ? L1 : L2;
        }
        __syncthreads();
        if (tid < NLABEL) s_chcnt[tid] = 0;
        if (tid == 0) s_chval = 0;
        __syncthreads();
        if (pk != 0) { atomicAdd(&s_chcnt[pk - 1], 1); atomicAdd(&s_chval, 1); }
        __syncthreads();
        if (tid < NLABEL) s_run[tid] += s_chcnt[tid];
        if (tid == 0) s_crun += s_chval;
        __syncthreads();
    }

    if (tid <= NLABEL) g_grpoff[b * (NLABEL + 1) + tid] = s_off[tid];
    /* pad region: deterministic sentinels */
    for (int k = tid; k < PP; k += blockDim.x)
        if (k >= K) {
            g_clab[b * PP + k] = -1;
            g_cnegcnt[b * PP + k] = 0;
            g_idxlast_orig[b * PP + k] = -1;
        }
}

/* ------------- K2: normalize rows -> bf16, compact layout [b][l][k][d] ------------- */
__global__ void k_norm(const float* __restrict__ meta) {
    int w = (blockIdx.x * blockDim.x + threadIdx.x) >> 5;
    int lane = threadIdx.x & 31;
    int b = w / (LL * PP); int rem = w % (LL * PP);
    int l = rem / PP; int k = rem % PP;
    size_t rowbase = ((size_t)(b * LL + l) * PP + k) * (DD / 8);
    int K = g_K[b];
    if (k >= K) {
        g_wh4[rowbase + lane] = make_uint4(0u, 0u, 0u, 0u);
        return;
    }
    int p = g_comp2orig[b * PP + k];
    int n = p >> 3, t = p & 7;
    const float* src = meta + ((((size_t)b * NN + n) * TT + t) * LL + l) * DD;
    float4 v0 = ((const float4*)src)[lane * 2];
    float4 v1 = ((const float4*)src)[lane * 2 + 1];
    float ss = v0.x*v0.x + v0.y*v0.y + v0.z*v0.z + v0.w*v0.w
             + v1.x*v1.x + v1.y*v1.y + v1.z*v1.z + v1.w*v1.w;
    for (int off = 16; off; off >>= 1) ss += __shfl_xor_sync(0xffffffffu, ss, off);
    float inv = 1.0f / fmaxf(sqrtf(ss), 1e-12f);
    v0.x*=inv; v0.y*=inv; v0.z*=inv; v0.w*=inv;
    v1.x*=inv; v1.y*=inv; v1.z*=inv; v1.w*=inv;
    __nv_bfloat162 h0 = __floats2bfloat162_rn(v0.x, v0.y);
    __nv_bfloat162 h1 = __floats2bfloat162_rn(v0.z, v0.w);
    __nv_bfloat162 h2 = __floats2bfloat162_rn(v1.x, v1.y);
    __nv_bfloat162 h3 = __floats2bfloat162_rn(v1.z, v1.w);
    uint4 o;
    o.x = *(uint32_t*)&h0; o.y = *(uint32_t*)&h1;
    o.z = *(uint32_t*)&h2; o.w = *(uint32_t*)&h3;
    g_wh4[rowbase + lane] = o;
}

/* ------------- K3: threefry (PARTITIONABLE mode) -> random positive pick ------------- */
__global__ void k_pick(const int* __restrict__ label) {
    int i = blockIdx.x * blockDim.x + threadIdx.x;
    if (i >= BLP) return;
    int b = i / (LL * PP); int rem = i % (LL * PP);
    int l = rem / PP; int p = rem % PP;
    int k = g_orig2comp[b * PP + p];
    if (k < 0) return;
    int pc = g_poscnt_orig[b * PP + p];
    int target;
    if (pc > 0) {
        uint32_t x0 = 0u, x1 = (uint32_t)i;
        threefry_0_42(x0, x1);
        uint32_t bits = x0 ^ x1;
        float u = __uint_as_float((bits >> 9) | 0x3F800000u) - 1.0f;
        int r = (int)floorf(u * (float)pc);
        if (r > pc - 1) r = pc - 1;
        if (r < 0) r = 0;
        int lab = label[b * PP + p];
        int start = g_grpoff[b * (NLABEL + 1) + lab];
        int j = g_posingrp[b * PP + p];
        int sel = (r < j) ? r : (r + 1);
        target = g_grpitems[b * PP + start + sel];
    } else {
        target = p;   /* diag fallback */
    }
    g_pospick[(b * LL + l) * PP + k] = g_orig2comp[b * PP + target];
}

/* ------------- K5: persistent HMMA GEMM + masked sum-exp + zp/zl -------------
 * 296 persistent CTAs grid-stride over live (b,l,rt) tiles only.
 * CTA: 256 threads, 8 warps (2x4). Tile BM=64 x BN=128, BK=32, warp tile 32x32.
 * A tile resident; B streamed 3-stage cp.async. Fragments double-buffered per
 * stage (all 8 LDSM up front, then 16 MMAs). LSE fixed reference point M0.
 */
#define BN_T 128
#define A_OFF    0        /* 8 stages x 4096 = 32768 */
#define B_OFF    32768    /* 3 bufs x 8192 = 24576 */
#define SLAB_OFF 57344    /* 2 x 512 label staging; reused for S reduction */
#define SMEM_DYN (58368 + 1024)
#define NPERSIST 296

__device__ __forceinline__ void prefetch_stage(int gidx, int nstages,
                                               const __nv_bfloat16* __restrict__ W,
                                               const int* __restrict__ clab,
                                               uint32_t sb, int tid) {
    if (gidx < nstages) {
        int ct2 = gidx >> 3, s2 = gidx & 7;
        uint32_t bbase = sb + B_OFF + (uint32_t)(gidx % 3) * 8192u;
#pragma unroll
        for (int j = 0; j < 2; j++) {
            int id = j * 256 + tid;
            int r = id >> 2, c = id & 3;
            const void* src = W + (size_t)(ct2 * BN_T + r) * DD + s2 * 32 + c * 8;
            uint32_t dst = bbase + (uint32_t)(r * 64) + (uint32_t)((c ^ ((r >> 1) & 3)) << 4);
            cp16(dst, src);
        }
        if (s2 == 0 && tid < 32) {
            const void* src = clab + ct2 * 128 + tid * 4;
            cp16(sb + SLAB_OFF + (uint32_t)((ct2 & 1) * 512 + tid * 16), src);
        }
    }
    CP_COMMIT();
}

__global__ void __launch_bounds__(256, 2) k_lse_hmma() {
    extern __shared__ char dsm[];
    uint32_t sraw = smem_u32(dsm);
    uint32_t sb = (sraw + 1023u) & ~1023u;
    char* amem = dsm + (sb - sraw);

    int tid = threadIdx.x;
    int wid = tid >> 5, lane = tid & 31;
    int mwarp = wid >> 2, nwarp = wid & 3;
    int g = lane >> 2, tg = lane & 3;
    int grp = lane >> 3, li = lane & 7;

    /* work-list prefix from g_K (uniform per thread) */
    int nrt[BB], woff[BB + 1];
    woff[0] = 0;
#pragma unroll
    for (int bb = 0; bb < BB; bb++) {
        nrt[bb] = (g_K[bb] + 63) >> 6;
        woff[bb + 1] = woff[bb] + LL * nrt[bb];
    }
    int nwork = woff[BB];

    /* item-independent fragment smem addresses */
    uint32_t rowA = (uint32_t)(mwarp * 32 + (grp & 1) * 8 + li);
    uint32_t cA = (uint32_t)(grp >> 1);
    uint32_t addrA0 = sb + A_OFF + rowA * 64u + ((cA ^ ((rowA >> 1) & 3u)) << 4);
    uint32_t rowB = (uint32_t)(nwarp * 32 + (grp >> 1) * 8 + li);
    uint32_t cB = (uint32_t)(grp & 1);
    uint32_t addrB0 = rowB * 64u + ((cB ^ ((rowB >> 1) & 3u)) << 4);

    for (int w = blockIdx.x; w < nwork; w += (int)gridDim.x) {
        int b = 0;
#pragma unroll
        for (int bb = 1; bb < BB; bb++) b += (w >= woff[bb]);
        int rem = w - woff[b], nr = nrt[b];
        int l = rem / nr, rt = rem - l * nr;
        int K = g_K[b];
        int row0 = rt * 64;
        int bl = b * LL + l;
        const __nv_bfloat16* W = (const __nv_bfloat16*)g_wh4 + (size_t)bl * PP * DD;
        const int* clab = g_clab + b * PP;

        int nct = (K + 127) >> 7;
        int nstages = nct * 8;

        /* per-thread row state (4 rows: mt in {0,1}, e in {0,1}) */
        int rloc[4], rlab[4], pick[4], last[4];
        float ssum[4];
#pragma unroll
        for (int i = 0; i < 4; i++) {
            int mt = i >> 1, e = i & 1;
            rloc[i] = mwarp * 32 + mt * 16 + g + 8 * e;
            int grow = row0 + rloc[i];
            rlab[i] = clab[grow];
            pick[i] = g_pospick[(size_t)bl * PP + grow];
            int lo = g_idxlast_orig[b * PP + grow];
            last[i] = (lo >= 0) ? g_orig2comp[b * PP + lo] : -2;
            ssum[i] = 0.f;
        }

        /* prologue: A (64x256) + B stage 0 in group 0; stage 1 in group 1 */
#pragma unroll
        for (int j = 0; j < 8; j++) {
            int id = j * 256 + tid;
            int s = id >> 8, rem2 = id & 255;
            int r = rem2 >> 2, c = rem2 & 3;
            const void* src = W + (size_t)(row0 + r) * DD + s * 32 + c * 8;
            uint32_t dst = sb + A_OFF + (uint32_t)(s * 4096 + r * 64)
                         + (uint32_t)((c ^ ((r >> 1) & 3)) << 4);
            cp16(dst, src);
        }
        prefetch_stage(0, nstages, W, clab, sb, tid);
        prefetch_stage(1, nstages, W, clab, sb, tid);

        float acc[2][4][4];
#pragma unroll
        for (int mt = 0; mt < 2; mt++)
#pragma unroll
            for (int nt = 0; nt < 4; nt++)
#pragma unroll
                for (int q = 0; q < 4; q++) acc[mt][nt][q] = 0.f;

        for (int ct = 0; ct < nct; ct++) {
            int col0 = ct * BN_T;
#pragma unroll 1
            for (int s = 0; s < 8; s++) {
                int gi = ct * 8 + s;
                CP_WAIT1();
                __syncthreads();
                prefetch_stage(gi + 2, nstages, W, clab, sb, tid);

                uint32_t aAddr = addrA0 + (uint32_t)(s * 4096);
                uint32_t bAddr = sb + B_OFF + (uint32_t)((gi % 3) * 8192) + addrB0;
                uint32_t a0[2][4], a1[2][4], bf[2][8];
#pragma unroll
                for (int kk = 0; kk < 2; kk++) {
                    uint32_t kx = (uint32_t)(kk * 32);
                    LDSM4(a0[kk][0], a0[kk][1], a0[kk][2], a0[kk][3], aAddr ^ kx);
                    LDSM4(a1[kk][0], a1[kk][1], a1[kk][2], a1[kk][3], (aAddr + 1024u) ^ kx);
                    LDSM4(bf[kk][0], bf[kk][1], bf[kk][2], bf[kk][3], bAddr ^ kx);
                    LDSM4(bf[kk][4], bf[kk][5], bf[kk][6], bf[kk][7], (bAddr + 1024u) ^ kx);
                }
#pragma unroll
                for (int kk = 0; kk < 2; kk++) {
#pragma unroll
                    for (int nt = 0; nt < 4; nt++) {
                        mma_bf16(acc[0][nt][0], acc[0][nt][1], acc[0][nt][2], acc[0][nt][3],
                                 a0[kk][0], a0[kk][1], a0[kk][2], a0[kk][3],
                                 bf[kk][nt * 2], bf[kk][nt * 2 + 1]);
                        mma_bf16(acc[1][nt][0], acc[1][nt][1], acc[1][nt][2], acc[1][nt][3],
                                 a1[kk][0], a1[kk][1], a1[kk][2], a1[kk][3],
                                 bf[kk][nt * 2], bf[kk][nt * 2 + 1]);
                    }
                }
            }

            /* ---- epilogue for this 64x128 tile ---- */
            const int* slabp = (const int*)(amem + SLAB_OFF + (ct & 1) * 512);
            int cls[8];
#pragma unroll
            for (int nt = 0; nt < 4; nt++)
#pragma unroll
                for (int q = 0; q < 2; q++)
                    cls[nt * 2 + q] = slabp[nwarp * 32 + nt * 8 + tg * 2 + q];

#pragma unroll
            for (int i = 0; i < 4; i++) {
                int mt = i >> 1, e = i & 1;
                int lr = rlab[i];
                size_t o = (size_t)bl * PP + row0 + rloc[i];
                float s4 = 0.f;
#pragma unroll
                for (int nt = 0; nt < 4; nt++) {
#pragma unroll
                    for (int q = 0; q < 2; q++) {
                        float av = acc[mt][nt][e * 2 + q];
                        int cl = cls[nt * 2 + q];
                        bool isneg = (cl >= 0) && (cl != lr);
                        float y = fmaf(av, C2LOG, -C2LOG);
                        y = isneg ? y : -110.0f;
                        s4 += exp2_poly(y);
                        int cg = col0 + nwarp * 32 + nt * 8 + tg * 2 + q;
                        if (cg == pick[i]) g_zp[o] = av * M0C;
                        if (cg == last[i]) g_zl[o] = av * M0C;
                    }
                }
                ssum[i] += s4;
            }
#pragma unroll
            for (int mt = 0; mt < 2; mt++)
#pragma unroll
                for (int nt = 0; nt < 4; nt++)
#pragma unroll
                    for (int q = 0; q < 4; q++) acc[mt][nt][q] = 0.f;
        }

        /* ---- writeback: reduce tg lanes, then across the 4 nwarp warps ---- */
        __syncthreads();                      /* slab label reads all done */
        float* sred = (float*)(amem + SLAB_OFF);   /* 8 warps x 32 rows */
#pragma unroll
        for (int i = 0; i < 4; i++) {
            float s = ssum[i];
            s += __shfl_xor_sync(0xffffffffu, s, 1);
            s += __shfl_xor_sync(0xffffffffu, s, 2);
            if (tg == 0) {
                int mt = i >> 1, e = i & 1;
                sred[wid * 32 + mt * 16 + g + 8 * e] = s;
            }
        }
        __syncthreads();
        if (tid < 64) {
            int mw = tid >> 5, r32 = tid & 31;
            float s = sred[(mw * 4 + 0) * 32 + r32] + sred[(mw * 4 + 1) * 32 + r32]
                    + sred[(mw * 4 + 2) * 32 + r32] + sred[(mw * 4 + 3) * 32 + r32];
            int grow = row0 + tid;
            if (grow < K)
                g_S[(size_t)bl * PP + grow] = s;
        }
        __syncthreads();                      /* smem safe for next item */
    }
}

/* ------------- K6: per-(b,l) loss reduction (fixed ref point M0) ------------- */
__global__ void k_final() {
    int bl = blockIdx.x; int b = bl / LL;
    int tid = threadIdx.x;
    int K = g_K[b];
    float acc = 0.f;
    for (int k = tid; k < K; k += blockDim.x) {
        size_t o = (size_t)bl * PP + k;
        float zp = g_zp[o], S = g_S[o];
        int negc = g_cnegcnt[b * PP + k];
        float ez = expf(zp - M0C);
        float padterm = 0.f;
        if (negc > 0) {
            int padi = K - 1 - negc; if (padi < 0) padi = 0;
            padterm = (float)padi * expf(g_zl[o] - M0C);
        } else {
            S = 0.f;
        }
        acc += M0C + logf(ez + S + padterm) - zp;
    }
    __shared__ float red[256];
    red[tid] = acc; __syncthreads();
    for (int s = 128; s; s >>= 1) {
        if (tid < s) red[tid] += red[tid + s];
        __syncthreads();
    }
    if (tid == 0) {
        int Kd = (K > 1) ? K : 1;
        g_partial[bl] = g_gate[b] ? (red[0] / (float)Kd) : 0.f;
    }
}

/* ------------- K7: final scalar ------------- */
__global__ void k_out(float* __restrict__ out) {
    __shared__ float red[64];
    int tid = threadIdx.x;
    red[tid] = (tid < BB * LL) ? g_partial[tid] : 0.f;
    __syncthreads();
    for (int s = 32; s; s >>= 1) {
        if (tid < s) red[tid] += red[tid + s];
        __syncthreads();
    }
    if (tid == 0) out[0] = red[0];
}

/* ------------------- launch ------------------- */
extern "C" void kernel_launch(void* const* d_in, const int* in_sizes, int n_in,
                              void* d_out, int out_size) {
    const float* meta = (const float*)d_in[0];
    const int* thing = (const int*)d_in[1];
    const int* label = (const int*)d_in[2];
    float* out = (float*)d_out;

    cudaFuncSetAttribute(k_lse_hmma, cudaFuncAttributeMaxDynamicSharedMemorySize, SMEM_DYN);

    k_meta<<<BB, 256>>>(thing, label);
    k_norm<<<(BB * LL * PP) / 8, 256>>>(meta);        /* 1 warp per row */
    k_pick<<<(BLP + 255) / 256, 256>>>(label);
    k_lse_hmma<<<NPERSIST, 256, SMEM_DYN>>>();
    k_final<<<BB * LL, 256>>>();
    k_out<<<1, 64>>>(out);
}

// round 8
// speedup vs baseline: 4.1111x; 1.0295x over previous
#include <cuda_runtime.h>
#include <cuda_bf16.h>
#include <stdint.h>

#define BB 8
#define NN 128
#define TT 8
#define LL 6
#define PP 1024
#define DD 256
#define NLABEL 40
#define BLP (BB*LL*PP)      /* 49152 */
#define M0C (1.0f/0.07f)
#define C2LOG (20.609929155556620f)   /* M0C * log2(e) */

/* ------------- device scratch (no allocations allowed) ------------- */
__device__ uint4 g_wh4[(size_t)BB*LL*PP*DD/8];  /* bf16 normalized rows */
__device__ int   g_K[BB];
__device__ int   g_gate[BB];
__device__ int   g_comp2orig[BB*PP];
__device__ int   g_orig2comp[BB*PP];
__device__ __align__(16) int g_clab[BB*PP];   /* labels by compact idx, pad=-1 */
__device__ int   g_cnegcnt[BB*PP];
__device__ int   g_poscnt_orig[BB*PP];
__device__ int   g_posingrp[BB*PP];
__device__ int   g_grpoff[BB*(NLABEL+1)];
__device__ int   g_grpitems[BB*PP];
__device__ int   g_idxlast_orig[BB*PP];       /* keyed by compact idx */
__device__ int   g_pospick[BLP];
__device__ float g_zp[BLP];
__device__ float g_zl[BLP];
__device__ float g_S[BLP];
__device__ float g_partial[BB*LL];

/* ------------------- helpers ------------------- */
__device__ __forceinline__ uint32_t rotl32(uint32_t x, int r) {
    return (x << r) | (x >> (32 - r));
}

/* JAX threefry2x32 with key = jax.random.key(42) -> (0, 42) */
__device__ __forceinline__ void threefry_0_42(uint32_t& x0, uint32_t& x1) {
    const uint32_t ks0 = 0u, ks1 = 42u, ks2 = 0u ^ 42u ^ 0x1BD11BDAu;
    x0 += ks0; x1 += ks1;
#define TF_RND(r) { x0 += x1; x1 = rotl32(x1, r); x1 ^= x0; }
    TF_RND(13) TF_RND(15) TF_RND(26) TF_RND(6)  x0 += ks1; x1 += ks2 + 1u;
    TF_RND(17) TF_RND(29) TF_RND(16) TF_RND(24) x0 += ks2; x1 += ks0 + 2u;
    TF_RND(13) TF_RND(15) TF_RND(26) TF_RND(6)  x0 += ks0; x1 += ks1 + 3u;
    TF_RND(17) TF_RND(29) TF_RND(16) TF_RND(24) x0 += ks1; x1 += ks2 + 4u;
    TF_RND(13) TF_RND(15) TF_RND(26) TF_RND(6)  x0 += ks2; x1 += ks0 + 5u;
#undef TF_RND
}

__device__ __forceinline__ void mma_bf16(float& d0, float& d1, float& d2, float& d3,
                                         uint32_t a0, uint32_t a1, uint32_t a2, uint32_t a3,
                                         uint32_t b0, uint32_t b1) {
    asm volatile(
        "mma.sync.aligned.m16n8k16.row.col.f32.bf16.bf16.f32 "
        "{%0,%1,%2,%3}, {%4,%5,%6,%7}, {%8,%9}, {%0,%1,%2,%3};"
        : "+f"(d0), "+f"(d1), "+f"(d2), "+f"(d3)
        : "r"(a0), "r"(a1), "r"(a2), "r"(a3), "r"(b0), "r"(b1));
}

#define LDSM4(r0, r1, r2, r3, addr) \
    asm volatile("ldmatrix.sync.aligned.m8n8.x4.shared.b16 {%0,%1,%2,%3}, [%4];" \
                 : "=r"(r0), "=r"(r1), "=r"(r2), "=r"(r3) : "r"(addr))

__device__ __forceinline__ void cp16(uint32_t dst, const void* src) {
    asm volatile("cp.async.cg.shared.global [%0], [%1], 16;" :: "r"(dst), "l"(src) : "memory");
}
#define CP_COMMIT() asm volatile("cp.async.commit_group;" ::: "memory")
#define CP_WAIT2()  asm volatile("cp.async.wait_group 2;" ::: "memory")

__device__ __forceinline__ uint32_t smem_u32(const void* p) {
    uint32_t a;
    asm("{ .reg .u64 t; cvta.to.shared.u64 t, %1; cvt.u32.u64 %0, t; }" : "=r"(a) : "l"(p));
    return a;
}

/* ------------------- K1: per-batch metadata (chunked rank scan) ------------------- */
__global__ void k_meta(const int* __restrict__ thing, const int* __restrict__ label) {
    int b = blockIdx.x, tid = threadIdx.x;
    __shared__ int s_pack[PP];          /* 0 = invalid, else label+1 */
    __shared__ int s_cnt[NLABEL];
    __shared__ int s_off[NLABEL + 1];
    __shared__ int s_run[NLABEL];
    __shared__ int s_chcnt[NLABEL];
    __shared__ int s_L1, s_L2, s_labL1, s_gate, s_K, s_crun, s_chval;
    if (tid < NLABEL) { s_cnt[tid] = 0; s_run[tid] = 0; }
    if (tid == 0) { s_L1 = -1; s_L2 = -1; s_gate = 0; s_crun = 0; }
    __syncthreads();
    for (int p = tid; p < PP; p += blockDim.x) {
        int v = thing[b * PP + p];
        int lab = label[b * PP + p];
        s_pack[p] = (v != 0) ? (lab + 1) : 0;
        if (v != 0) { atomicAdd(&s_cnt[lab], 1); atomicMax(&s_L1, p); }
    }
    for (int n = tid; n < NN; n += blockDim.x) {
        int ss = 0;
        for (int t = 0; t < TT; t++) ss += thing[(b * NN + n) * TT + t];
        if (ss > 0) atomicAdd(&s_gate, 1);
    }
    __syncthreads();
    if (tid == 0) {
        int acc = 0;
        for (int v = 0; v < NLABEL; v++) { s_off[v] = acc; acc += s_cnt[v]; }
        s_off[NLABEL] = acc; s_K = acc;
        g_K[b] = acc;
        g_gate[b] = (s_gate >= 2) ? 1 : 0;
        s_labL1 = (s_L1 >= 0) ? (s_pack[s_L1] - 1) : -1;
    }
    __syncthreads();
    int labL1 = s_labL1;
    for (int p = tid; p < PP; p += blockDim.x) {
        int pk = s_pack[p];
        if (pk != 0 && (pk - 1) != labL1) atomicMax(&s_L2, p);
    }
    __syncthreads();
    int K = s_K, L1 = s_L1, L2 = s_L2;

    /* ranks via 4 sequential chunks of 256 with running prefixes */
    for (int c = 0; c < 4; c++) {
        int base = c * 256;
        int p = base + tid;
        int pk = s_pack[p];
        int crloc = 0, grloc = 0;
        for (int q = base; q < p; q++) {
            int qk = s_pack[q];
            crloc += (qk != 0);
            grloc += (qk == pk);
        }
        if (pk == 0) {
            g_orig2comp[b * PP + p] = -1;
        } else {
            int lab = pk - 1;
            int crank = s_crun + crloc;
            int grank = s_run[lab] + grloc;
            g_orig2comp[b * PP + p] = crank;
            g_comp2orig[b * PP + crank] = p;
            g_clab[b * PP + crank] = lab;
            int cl = s_cnt[lab];
            g_poscnt_orig[b * PP + p] = cl - 1;
            g_cnegcnt[b * PP + crank] = K - cl;
            g_posingrp[b * PP + p] = grank;
            g_grpitems[b * PP + s_off[lab] + grank] = p;
            g_idxlast_orig[b * PP + crank] = (lab != labL1) ? L1 : L2;
        }
        __syncthreads();
        if (tid < NLABEL) s_chcnt[tid] = 0;
        if (tid == 0) s_chval = 0;
        __syncthreads();
        if (pk != 0) { atomicAdd(&s_chcnt[pk - 1], 1); atomicAdd(&s_chval, 1); }
        __syncthreads();
        if (tid < NLABEL) s_run[tid] += s_chcnt[tid];
        if (tid == 0) s_crun += s_chval;
        __syncthreads();
    }

    if (tid <= NLABEL) g_grpoff[b * (NLABEL + 1) + tid] = s_off[tid];
    /* pad region: deterministic sentinels */
    for (int k = tid; k < PP; k += blockDim.x)
        if (k >= K) {
            g_clab[b * PP + k] = -1;
            g_cnegcnt[b * PP + k] = 0;
            g_idxlast_orig[b * PP + k] = -1;
        }
}

/* ------------- K2: normalize rows -> bf16, compact layout [b][l][k][d] ------------- */
__global__ void k_norm(const float* __restrict__ meta) {
    int w = (blockIdx.x * blockDim.x + threadIdx.x) >> 5;
    int lane = threadIdx.x & 31;
    int b = w / (LL * PP); int rem = w % (LL * PP);
    int l = rem / PP; int k = rem % PP;
    size_t rowbase = ((size_t)(b * LL + l) * PP + k) * (DD / 8);
    int K = g_K[b];
    if (k >= K) {
        g_wh4[rowbase + lane] = make_uint4(0u, 0u, 0u, 0u);
        return;
    }
    int p = g_comp2orig[b * PP + k];
    int n = p >> 3, t = p & 7;
    const float* src = meta + ((((size_t)b * NN + n) * TT + t) * LL + l) * DD;
    float4 v0 = ((const float4*)src)[lane * 2];
    float4 v1 = ((const float4*)src)[lane * 2 + 1];
    float ss = v0.x*v0.x + v0.y*v0.y + v0.z*v0.z + v0.w*v0.w
             + v1.x*v1.x + v1.y*v1.y + v1.z*v1.z + v1.w*v1.w;
    for (int off = 16; off; off >>= 1) ss += __shfl_xor_sync(0xffffffffu, ss, off);
    float inv = 1.0f / fmaxf(sqrtf(ss), 1e-12f);
    v0.x*=inv; v0.y*=inv; v0.z*=inv; v0.w*=inv;
    v1.x*=inv; v1.y*=inv; v1.z*=inv; v1.w*=inv;
    __nv_bfloat162 h0 = __floats2bfloat162_rn(v0.x, v0.y);
    __nv_bfloat162 h1 = __floats2bfloat162_rn(v0.z, v0.w);
    __nv_bfloat162 h2 = __floats2bfloat162_rn(v1.x, v1.y);
    __nv_bfloat162 h3 = __floats2bfloat162_rn(v1.z, v1.w);
    uint4 o;
    o.x = *(uint32_t*)&h0; o.y = *(uint32_t*)&h1;
    o.z = *(uint32_t*)&h2; o.w = *(uint32_t*)&h3;
    g_wh4[rowbase + lane] = o;
}

/* ------------- K3: threefry (PARTITIONABLE mode) -> random positive pick ------------- */
__global__ void k_pick(const int* __restrict__ label) {
    int i = blockIdx.x * blockDim.x + threadIdx.x;
    if (i >= BLP) return;
    int b = i / (LL * PP); int rem = i % (LL * PP);
    int l = rem / PP; int p = rem % PP;
    int k = g_orig2comp[b * PP + p];
    if (k < 0) return;
    int pc = g_poscnt_orig[b * PP + p];
    int target;
    if (pc > 0) {
        uint32_t x0 = 0u, x1 = (uint32_t)i;
        threefry_0_42(x0, x1);
        uint32_t bits = x0 ^ x1;
        float u = __uint_as_float((bits >> 9) | 0x3F800000u) - 1.0f;
        int r = (int)floorf(u * (float)pc);
        if (r > pc - 1) r = pc - 1;
        if (r < 0) r = 0;
        int lab = label[b * PP + p];
        int start = g_grpoff[b * (NLABEL + 1) + lab];
        int j = g_posingrp[b * PP + p];
        int sel = (r < j) ? r : (r + 1);
        target = g_grpitems[b * PP + start + sel];
    } else {
        target = p;   /* diag fallback */
    }
    g_pospick[(b * LL + l) * PP + k] = g_orig2comp[b * PP + target];
}

/* ------------- K5: persistent HMMA GEMM + masked sum-exp + zp/zl -------------
 * 296 persistent CTAs grid-stride over live (b,l,rt) tiles only.
 * CTA: 256 threads, 8 warps (2x4). Tile BM=64 x BN=128, warp tile 32x32.
 * A tile resident; B streamed in 16KB stages (two 8KB sub-blocks), 4-buffer
 * cp.async ring, one barrier per 16KB. Labels in 3-slot ring.
 * Epilogue: magic-number exp2 (FMA pipe only), deg-4 Taylor, pair-tested zp/zl.
 */
#define BN_T 128
#define A_OFF    0         /* 8 x 4096 = 32768 */
#define B_OFF    32768     /* 4 bufs x 16384 = 65536 */
#define SLAB_OFF 98304     /* 3 x 512 label ring */
#define SRED_OFF 99840     /* 8 warps x 32 rows x 4B = 1024 */
#define SMEM_DYN (100864 + 1024)
#define NPERSIST 296

__device__ __forceinline__ void prefetch_pair(int stp, int nstp,
                                              const __nv_bfloat16* __restrict__ W,
                                              const int* __restrict__ clab,
                                              uint32_t sb, int tid) {
    if (stp < nstp) {
        uint32_t bbase = sb + B_OFF + (uint32_t)(stp & 3) * 16384u;
#pragma unroll
        for (int h = 0; h < 2; h++) {
            int gsub = 2 * stp + h;
            int ct2 = gsub >> 3, s2 = gsub & 7;
#pragma unroll
            for (int j = 0; j < 2; j++) {
                int id = j * 256 + tid;
                int r = id >> 2, c = id & 3;
                const void* src = W + (size_t)(ct2 * 128 + r) * DD + s2 * 32 + c * 8;
                uint32_t dst = bbase + (uint32_t)(h * 8192 + r * 64)
                             + (uint32_t)((c ^ ((r >> 1) & 3)) << 4);
                cp16(dst, src);
            }
            if ((gsub & 7) == 0 && tid < 32) {
                cp16(sb + SLAB_OFF + (uint32_t)((ct2 % 3) * 512 + tid * 16),
                     clab + ct2 * 128 + tid * 4);
            }
        }
    }
    CP_COMMIT();
}

__global__ void __launch_bounds__(256, 2) k_lse_hmma() {
    extern __shared__ char dsm[];
    uint32_t sraw = smem_u32(dsm);
    uint32_t sb = (sraw + 1023u) & ~1023u;
    char* amem = dsm + (sb - sraw);

    int tid = threadIdx.x;
    int wid = tid >> 5, lane = tid & 31;
    int mwarp = wid >> 2, nwarp = wid & 3;
    int g = lane >> 2, tg = lane & 3;
    int grp = lane >> 3, li = lane & 7;

    /* work-list prefix from g_K (uniform per thread) */
    int nrt[BB], woff[BB + 1];
    woff[0] = 0;
#pragma unroll
    for (int bb = 0; bb < BB; bb++) {
        nrt[bb] = (g_K[bb] + 63) >> 6;
        woff[bb + 1] = woff[bb] + LL * nrt[bb];
    }
    int nwork = woff[BB];

    /* item-independent fragment smem addresses */
    uint32_t rowA = (uint32_t)(mwarp * 32 + (grp & 1) * 8 + li);
    uint32_t cA = (uint32_t)(grp >> 1);
    uint32_t addrA0 = sb + A_OFF + rowA * 64u + ((cA ^ ((rowA >> 1) & 3u)) << 4);
    uint32_t rowB = (uint32_t)(nwarp * 32 + (grp >> 1) * 8 + li);
    uint32_t cB = (uint32_t)(grp & 1);
    uint32_t addrB0 = rowB * 64u + ((cB ^ ((rowB >> 1) & 3u)) << 4);

    for (int w = blockIdx.x; w < nwork; w += (int)gridDim.x) {
        int b = 0;
#pragma unroll
        for (int bb = 1; bb < BB; bb++) b += (w >= woff[bb]);
        int rem = w - woff[b], nr = nrt[b];
        int l = rem / nr, rt = rem - l * nr;
        int K = g_K[b];
        int row0 = rt * 64;
        int bl = b * LL + l;
        const __nv_bfloat16* W = (const __nv_bfloat16*)g_wh4 + (size_t)bl * PP * DD;
        const int* clab = g_clab + b * PP;

        int nct = (K + 127) >> 7;
        int nstp = nct * 4;

        /* per-thread row state (4 rows: mt in {0,1}, e in {0,1}) */
        int rloc[4], rlab[4], pick[4], last[4];
        float ssum[4];
#pragma unroll
        for (int i = 0; i < 4; i++) {
            int mt = i >> 1, e = i & 1;
            rloc[i] = mwarp * 32 + mt * 16 + g + 8 * e;
            int grow = row0 + rloc[i];
            rlab[i] = clab[grow];
            pick[i] = g_pospick[(size_t)bl * PP + grow];
            int lo = g_idxlast_orig[b * PP + grow];
            last[i] = (lo >= 0) ? g_orig2comp[b * PP + lo] : -2;
            ssum[i] = 0.f;
        }

        /* prologue: A (64x256) bundled with stage 0; stages 1, 2 */
#pragma unroll
        for (int j = 0; j < 8; j++) {
            int id = j * 256 + tid;
            int s = id >> 8, rem2 = id & 255;
            int r = rem2 >> 2, c = rem2 & 3;
            const void* src = W + (size_t)(row0 + r) * DD + s * 32 + c * 8;
            uint32_t dst = sb + A_OFF + (uint32_t)(s * 4096 + r * 64)
                         + (uint32_t)((c ^ ((r >> 1) & 3)) << 4);
            cp16(dst, src);
        }
        prefetch_pair(0, nstp, W, clab, sb, tid);
        prefetch_pair(1, nstp, W, clab, sb, tid);
        prefetch_pair(2, nstp, W, clab, sb, tid);

        float acc[2][4][4];
#pragma unroll
        for (int mt = 0; mt < 2; mt++)
#pragma unroll
            for (int nt = 0; nt < 4; nt++)
#pragma unroll
                for (int q = 0; q < 4; q++) acc[mt][nt][q] = 0.f;

#pragma unroll 1
        for (int st = 0; st < nstp; st++) {
            CP_WAIT2();
            __syncthreads();
            prefetch_pair(st + 3, nstp, W, clab, sb, tid);

            uint32_t bbase = sb + B_OFF + (uint32_t)(st & 3) * 16384u;
#pragma unroll
            for (int h = 0; h < 2; h++) {
                int s2 = (2 * st + h) & 7;
                uint32_t aAddr = addrA0 + (uint32_t)(s2 * 4096);
                uint32_t bAddr = bbase + (uint32_t)(h * 8192) + addrB0;
#pragma unroll
                for (int kk = 0; kk < 2; kk++) {
                    uint32_t kx = (uint32_t)(kk * 32);
                    uint32_t a0[4], a1[4], bf[8];
                    LDSM4(a0[0], a0[1], a0[2], a0[3], aAddr ^ kx);
                    LDSM4(a1[0], a1[1], a1[2], a1[3], (aAddr + 1024u) ^ kx);
                    LDSM4(bf[0], bf[1], bf[2], bf[3], bAddr ^ kx);
                    LDSM4(bf[4], bf[5], bf[6], bf[7], (bAddr + 1024u) ^ kx);
#pragma unroll
                    for (int nt = 0; nt < 4; nt++) {
                        mma_bf16(acc[0][nt][0], acc[0][nt][1], acc[0][nt][2], acc[0][nt][3],
                                 a0[0], a0[1], a0[2], a0[3], bf[nt * 2], bf[nt * 2 + 1]);
                        mma_bf16(acc[1][nt][0], acc[1][nt][1], acc[1][nt][2], acc[1][nt][3],
                                 a1[0], a1[1], a1[2], a1[3], bf[nt * 2], bf[nt * 2 + 1]);
                    }
                }
            }

            if ((st & 3) == 3) {
                /* ---- epilogue for col tile ct ---- */
                int ct = st >> 2;
                int col0 = ct * BN_T;
                const int* slabp = (const int*)(amem + SLAB_OFF + (ct % 3) * 512);
                int cls[8];
#pragma unroll
                for (int nt = 0; nt < 4; nt++)
#pragma unroll
                    for (int q = 0; q < 2; q++)
                        cls[nt * 2 + q] = slabp[nwarp * 32 + nt * 8 + tg * 2 + q];

                int cgb = col0 + nwarp * 32 + tg * 2;
#pragma unroll
                for (int i = 0; i < 4; i++) {
                    int mt = i >> 1, e = i & 1;
                    int lr = rlab[i];
                    size_t o = (size_t)bl * PP + row0 + rloc[i];
                    float s4 = 0.f;
#pragma unroll
                    for (int nt = 0; nt < 4; nt++) {
                        float z0 = acc[mt][nt][e * 2 + 0];
                        float z1 = acc[mt][nt][e * 2 + 1];
                        int cg0 = cgb + nt * 8;
                        unsigned dp = (unsigned)(pick[i] - cg0);
                        unsigned dl = (unsigned)(last[i] - cg0);
                        if (dp < 2u) g_zp[o] = (dp ? z1 : z0) * M0C;
                        if (dl < 2u) g_zl[o] = (dl ? z1 : z0) * M0C;
#pragma unroll
                        for (int q = 0; q < 2; q++) {
                            float av = q ? z1 : z0;
                            int cl = cls[nt * 2 + q];
                            bool isneg = (cl >= 0) && (cl != lr);
                            float y = fmaf(av, C2LOG, -C2LOG);
                            y = isneg ? y : -110.0f;
                            float t = y + 12582912.0f;      /* RN magic */
                            float nf = t - 12582912.0f;
                            float f = y - nf;
                            float p = 9.6181291076e-3f;
                            p = fmaf(p, f, 5.5504108664e-2f);
                            p = fmaf(p, f, 2.4022650695e-1f);
                            p = fmaf(p, f, 6.9314718056e-1f);
                            p = fmaf(p, f, 1.0f);
                            int rbits = __float_as_int(p) + (__float_as_int(t) << 23);
                            s4 += __int_as_float(rbits);
                        }
                    }
                    ssum[i] += s4;
                }
#pragma unroll
                for (int mt = 0; mt < 2; mt++)
#pragma unroll
                    for (int nt = 0; nt < 4; nt++)
#pragma unroll
                        for (int q = 0; q < 4; q++) acc[mt][nt][q] = 0.f;
            }
        }

        /* ---- writeback: reduce tg lanes, then across the 4 nwarp warps ---- */
        float* sred = (float*)(amem + SRED_OFF);   /* 8 warps x 32 rows */
#pragma unroll
        for (int i = 0; i < 4; i++) {
            float s = ssum[i];
            s += __shfl_xor_sync(0xffffffffu, s, 1);
            s += __shfl_xor_sync(0xffffffffu, s, 2);
            if (tg == 0) {
                int mt = i >> 1, e = i & 1;
                sred[wid * 32 + mt * 16 + g + 8 * e] = s;
            }
        }
        __syncthreads();
        if (tid < 64) {
            int mw = tid >> 5, r32 = tid & 31;
            float s = sred[(mw * 4 + 0) * 32 + r32] + sred[(mw * 4 + 1) * 32 + r32]
                    + sred[(mw * 4 + 2) * 32 + r32] + sred[(mw * 4 + 3) * 32 + r32];
            int grow = row0 + tid;
            if (grow < K)
                g_S[(size_t)bl * PP + grow] = s;
        }
        __syncthreads();                      /* smem safe for next item */
    }
}

/* ------------- K6: per-(b,l) loss reduction (fixed ref point M0) ------------- */
__global__ void k_final() {
    int bl = blockIdx.x; int b = bl / LL;
    int tid = threadIdx.x;
    int K = g_K[b];
    float acc = 0.f;
    for (int k = tid; k < K; k += blockDim.x) {
        size_t o = (size_t)bl * PP + k;
        float zp = g_zp[o], S = g_S[o];
        int negc = g_cnegcnt[b * PP + k];
        float ez = expf(zp - M0C);
        float padterm = 0.f;
        if (negc > 0) {
            int padi = K - 1 - negc; if (padi < 0) padi = 0;
            padterm = (float)padi * expf(g_zl[o] - M0C);
        } else {
            S = 0.f;
        }
        acc += M0C + logf(ez + S + padterm) - zp;
    }
    __shared__ float red[256];
    red[tid] = acc; __syncthreads();
    for (int s = 128; s; s >>= 1) {
        if (tid < s) red[tid] += red[tid + s];
        __syncthreads();
    }
    if (tid == 0) {
        int Kd = (K > 1) ? K : 1;
        g_partial[bl] = g_gate[b] ? (red[0] / (float)Kd) : 0.f;
    }
}

/* ------------- K7: final scalar ------------- */
__global__ void k_out(float* __restrict__ out) {
    __shared__ float red[64];
    int tid = threadIdx.x;
    red[tid] = (tid < BB * LL) ? g_partial[tid] : 0.f;
    __syncthreads();
    for (int s = 32; s; s >>= 1) {
        if (tid < s) red[tid] += red[tid + s];
        __syncthreads();
    }
    if (tid == 0) out[0] = red[0];
}

/* ------------------- launch ------------------- */
extern "C" void kernel_launch(void* const* d_in, const int* in_sizes, int n_in,
                              void* d_out, int out_size) {
    const float* meta = (const float*)d_in[0];
    const int* thing = (const int*)d_in[1];
    const int* label = (const int*)d_in[2];
    float* out = (float*)d_out;

    cudaFuncSetAttribute(k_lse_hmma, cudaFuncAttributeMaxDynamicSharedMemorySize, SMEM_DYN);

    k_meta<<<BB, 256>>>(thing, label);
    k_norm<<<(BB * LL * PP) / 8, 256>>>(meta);        /* 1 warp per row */
    k_pick<<<(BLP + 255) / 256, 256>>>(label);
    k_lse_hmma<<<NPERSIST, 256, SMEM_DYN>>>();
    k_final<<<BB * LL, 256>>>();
    k_out<<<1, 64>>>(out);
}